// round 1
// baseline (speedup 1.0000x reference)
#include <cuda_runtime.h>
#include <math.h>

#define Bn 4
#define Cn 512
#define Nn 4096
#define TWO_C 1024

constexpr size_t SZ_BCN = (size_t)Bn * Cn * Nn;        // 8,388,608
constexpr size_t SZ_GB  = (size_t)Bn * TWO_C * Nn;     // 16,777,216
constexpr size_t SZ_S   = (size_t)Bn * Nn * Nn;        // 67,108,864

// Scratch (static __device__ arrays; no runtime allocation allowed)
__device__ float g_NC[SZ_BCN];    // inst-normed content
__device__ float g_NS[SZ_BCN];    // inst-normed style
__device__ float g_Q[SZ_BCN];
__device__ float g_K[SZ_BCN];
__device__ float g_V[SZ_BCN];
__device__ float g_STY[SZ_BCN];   // attention output
__device__ float g_GB[SZ_GB];     // stacked gamma(0..C) / beta(C..2C) per batch
__device__ float g_S[SZ_S];       // scores / softmax probs
__device__ float g_WtQ[Cn * Cn];  // transposed weights (K-major)
__device__ float g_WtK[Cn * Cn];
__device__ float g_WtV[Cn * Cn];
__device__ float g_WtGB[Cn * TWO_C];
__device__ float g_bGB[TWO_C];

// ---------------------------------------------------------------------------
// Instance norm: one block per (b,c), 256 threads over 4096 elements.
// ---------------------------------------------------------------------------
__global__ void instnorm_kernel(const float* __restrict__ x, float* __restrict__ y) {
    const int tid = threadIdx.x;
    const size_t base = (size_t)blockIdx.x * Nn;
    float v[16];
    float s = 0.f, s2 = 0.f;
#pragma unroll
    for (int i = 0; i < 16; ++i) {
        float t = x[base + tid + i * 256];
        v[i] = t; s += t; s2 += t * t;
    }
#pragma unroll
    for (int o = 16; o > 0; o >>= 1) {
        s  += __shfl_xor_sync(0xffffffffu, s, o);
        s2 += __shfl_xor_sync(0xffffffffu, s2, o);
    }
    __shared__ float sh[16];
    int warp = tid >> 5, lane = tid & 31;
    if (lane == 0) { sh[warp] = s; sh[8 + warp] = s2; }
    __syncthreads();
    if (tid == 0) {
        float S = 0.f, S2 = 0.f;
        for (int w = 0; w < 8; ++w) { S += sh[w]; S2 += sh[8 + w]; }
        sh[0] = S; sh[8] = S2;
    }
    __syncthreads();
    float mean = sh[0] * (1.f / Nn);
    float var  = sh[8] * (1.f / Nn) - mean * mean;
    float inv  = rsqrtf(var + 1e-5f);
#pragma unroll
    for (int i = 0; i < 16; ++i)
        y[base + tid + i * 256] = (v[i] - mean) * inv;
}

// ---------------------------------------------------------------------------
// Weight transpose: W[M,K] (row-major) -> Wt[k*ldo + mofs + m]
// blockDim (32,8), grid (K/32, M/32)
// ---------------------------------------------------------------------------
__global__ void transpose_kernel(const float* __restrict__ W, float* __restrict__ Wt,
                                 int M, int K, int ldo, int mofs) {
    __shared__ float tile[32][33];
    int k0 = blockIdx.x * 32, m0 = blockIdx.y * 32;
#pragma unroll
    for (int j = 0; j < 4; ++j) {
        int m = m0 + threadIdx.y + 8 * j;
        tile[threadIdx.y + 8 * j][threadIdx.x] = W[(size_t)m * K + k0 + threadIdx.x];
    }
    __syncthreads();
#pragma unroll
    for (int j = 0; j < 4; ++j) {
        int k = k0 + threadIdx.y + 8 * j;
        Wt[(size_t)k * ldo + mofs + m0 + threadIdx.x] = tile[threadIdx.x][threadIdx.y + 8 * j];
    }
}

__global__ void biasstack_kernel(const float* __restrict__ bg, const float* __restrict__ bb,
                                 float* __restrict__ out) {
    int i = threadIdx.x;  // 1024 threads
    out[i] = (i < Cn) ? bg[i] : bb[i - Cn];
}

// ---------------------------------------------------------------------------
// GEMM-TN: C[m,n] = sum_k A[k*lda + m] * B[k*ldb + n]  (+bias[m], optional relu)
// 128x128 tile, BK=8, 256 threads, 8x8 microtile.
// ---------------------------------------------------------------------------
__global__ void __launch_bounds__(256, 2)
gemm_tn_kernel(const float* __restrict__ A, size_t strideA, int lda,
               const float* __restrict__ B, size_t strideB, int ldb,
               float* __restrict__ C, size_t strideC, int ldc,
               const float* __restrict__ bias, int Kdim, int relu) {
    __shared__ float As[8][128];
    __shared__ float Bs[8][128];

    const float* Ab = A + (size_t)blockIdx.z * strideA;
    const float* Bb = B + (size_t)blockIdx.z * strideB;
    float* Cb = C + (size_t)blockIdx.z * strideC;

    const int m0 = blockIdx.y * 128, n0 = blockIdx.x * 128;
    const int t = threadIdx.x;
    const int lr = t >> 5;           // k row 0..7
    const int lc = (t & 31) << 2;    // col offset 0..124
    const int ty = t >> 4, tx = t & 15;

    float acc[8][8];
#pragma unroll
    for (int i = 0; i < 8; ++i)
#pragma unroll
        for (int j = 0; j < 8; ++j) acc[i][j] = 0.f;

    const float* Aptr = Ab + (size_t)lr * lda + m0 + lc;
    const float* Bptr = Bb + (size_t)lr * ldb + n0 + lc;

    for (int k0 = 0; k0 < Kdim; k0 += 8) {
        float4 a = *(const float4*)Aptr;
        float4 b = *(const float4*)Bptr;
        *(float4*)&As[lr][lc] = a;
        *(float4*)&Bs[lr][lc] = b;
        __syncthreads();
        float ar[8], br[8];
#pragma unroll
        for (int kk = 0; kk < 8; ++kk) {
            *(float4*)&ar[0] = *(float4*)&As[kk][ty * 4];
            *(float4*)&ar[4] = *(float4*)&As[kk][64 + ty * 4];
            *(float4*)&br[0] = *(float4*)&Bs[kk][tx * 4];
            *(float4*)&br[4] = *(float4*)&Bs[kk][64 + tx * 4];
#pragma unroll
            for (int i = 0; i < 8; ++i)
#pragma unroll
                for (int j = 0; j < 8; ++j)
                    acc[i][j] += ar[i] * br[j];
        }
        __syncthreads();
        Aptr += (size_t)8 * lda;
        Bptr += (size_t)8 * ldb;
    }

#pragma unroll
    for (int ih = 0; ih < 2; ++ih) {
#pragma unroll
        for (int i = 0; i < 4; ++i) {
            int m = m0 + ih * 64 + ty * 4 + i;
            float bv = bias ? bias[m] : 0.f;
            float4 r0, r1;
            r0.x = acc[ih * 4 + i][0] + bv; r0.y = acc[ih * 4 + i][1] + bv;
            r0.z = acc[ih * 4 + i][2] + bv; r0.w = acc[ih * 4 + i][3] + bv;
            r1.x = acc[ih * 4 + i][4] + bv; r1.y = acc[ih * 4 + i][5] + bv;
            r1.z = acc[ih * 4 + i][6] + bv; r1.w = acc[ih * 4 + i][7] + bv;
            if (relu) {
                r0.x = fmaxf(r0.x, 0.f); r0.y = fmaxf(r0.y, 0.f);
                r0.z = fmaxf(r0.z, 0.f); r0.w = fmaxf(r0.w, 0.f);
                r1.x = fmaxf(r1.x, 0.f); r1.y = fmaxf(r1.y, 0.f);
                r1.z = fmaxf(r1.z, 0.f); r1.w = fmaxf(r1.w, 0.f);
            }
            *(float4*)&Cb[(size_t)m * ldc + n0 + tx * 4] = r0;
            *(float4*)&Cb[(size_t)m * ldc + n0 + 64 + tx * 4] = r1;
        }
    }
}

// ---------------------------------------------------------------------------
// GEMM-NT: C[m,n] = sum_k A[m*lda + k] * B[n*ldb + k]
// Same tiling; global loads along k, transposed into smem.
// ---------------------------------------------------------------------------
__global__ void __launch_bounds__(256, 2)
gemm_nt_kernel(const float* __restrict__ A, size_t strideA, int lda,
               const float* __restrict__ B, size_t strideB, int ldb,
               float* __restrict__ C, size_t strideC, int ldc,
               int Kdim) {
    __shared__ float As[8][128];
    __shared__ float Bs[8][128];

    const float* Ab = A + (size_t)blockIdx.z * strideA;
    const float* Bb = B + (size_t)blockIdx.z * strideB;
    float* Cb = C + (size_t)blockIdx.z * strideC;

    const int m0 = blockIdx.y * 128, n0 = blockIdx.x * 128;
    const int t = threadIdx.x;
    const int row = t >> 1;          // 0..127
    const int kq  = (t & 1) * 4;     // 0 or 4
    const int ty = t >> 4, tx = t & 15;

    float acc[8][8];
#pragma unroll
    for (int i = 0; i < 8; ++i)
#pragma unroll
        for (int j = 0; j < 8; ++j) acc[i][j] = 0.f;

    const float* Aptr = Ab + (size_t)(m0 + row) * lda + kq;
    const float* Bptr = Bb + (size_t)(n0 + row) * ldb + kq;

    for (int k0 = 0; k0 < Kdim; k0 += 8) {
        float4 a = *(const float4*)Aptr;
        float4 b = *(const float4*)Bptr;
        As[kq + 0][row] = a.x; As[kq + 1][row] = a.y;
        As[kq + 2][row] = a.z; As[kq + 3][row] = a.w;
        Bs[kq + 0][row] = b.x; Bs[kq + 1][row] = b.y;
        Bs[kq + 2][row] = b.z; Bs[kq + 3][row] = b.w;
        __syncthreads();
        float ar[8], br[8];
#pragma unroll
        for (int kk = 0; kk < 8; ++kk) {
            *(float4*)&ar[0] = *(float4*)&As[kk][ty * 4];
            *(float4*)&ar[4] = *(float4*)&As[kk][64 + ty * 4];
            *(float4*)&br[0] = *(float4*)&Bs[kk][tx * 4];
            *(float4*)&br[4] = *(float4*)&Bs[kk][64 + tx * 4];
#pragma unroll
            for (int i = 0; i < 8; ++i)
#pragma unroll
                for (int j = 0; j < 8; ++j)
                    acc[i][j] += ar[i] * br[j];
        }
        __syncthreads();
        Aptr += 8;
        Bptr += 8;
    }

#pragma unroll
    for (int ih = 0; ih < 2; ++ih) {
#pragma unroll
        for (int i = 0; i < 4; ++i) {
            int m = m0 + ih * 64 + ty * 4 + i;
            float4 r0, r1;
            r0.x = acc[ih * 4 + i][0]; r0.y = acc[ih * 4 + i][1];
            r0.z = acc[ih * 4 + i][2]; r0.w = acc[ih * 4 + i][3];
            r1.x = acc[ih * 4 + i][4]; r1.y = acc[ih * 4 + i][5];
            r1.z = acc[ih * 4 + i][6]; r1.w = acc[ih * 4 + i][7];
            *(float4*)&Cb[(size_t)m * ldc + n0 + tx * 4] = r0;
            *(float4*)&Cb[(size_t)m * ldc + n0 + 64 + tx * 4] = r1;
        }
    }
}

// ---------------------------------------------------------------------------
// Row softmax over 4096 elements; one block per row, 256 threads.
// ---------------------------------------------------------------------------
__global__ void softmax_kernel(float* __restrict__ S) {
    const int tid = threadIdx.x;
    float* row = S + (size_t)blockIdx.x * Nn;
    float v[16];
    float mx = -INFINITY;
#pragma unroll
    for (int i = 0; i < 16; ++i) {
        v[i] = row[tid + i * 256];
        mx = fmaxf(mx, v[i]);
    }
#pragma unroll
    for (int o = 16; o > 0; o >>= 1)
        mx = fmaxf(mx, __shfl_xor_sync(0xffffffffu, mx, o));
    __shared__ float sh[16];
    int warp = tid >> 5, lane = tid & 31;
    if (lane == 0) sh[warp] = mx;
    __syncthreads();
    if (tid == 0) {
        float m = sh[0];
        for (int w = 1; w < 8; ++w) m = fmaxf(m, sh[w]);
        sh[0] = m;
    }
    __syncthreads();
    mx = sh[0];
    float s = 0.f;
#pragma unroll
    for (int i = 0; i < 16; ++i) {
        v[i] = expf(v[i] - mx);
        s += v[i];
    }
#pragma unroll
    for (int o = 16; o > 0; o >>= 1)
        s += __shfl_xor_sync(0xffffffffu, s, o);
    if (lane == 0) sh[8 + warp] = s;
    __syncthreads();
    if (tid == 0) {
        float t = 0.f;
        for (int w = 0; w < 8; ++w) t += sh[8 + w];
        sh[8] = t;
    }
    __syncthreads();
    float inv = 1.f / sh[8];
#pragma unroll
    for (int i = 0; i < 16; ++i)
        row[tid + i * 256] = v[i] * inv;
}

// ---------------------------------------------------------------------------
// Final combine: out = (NC*sw[c] + sb[c]) * gamma + beta
// ---------------------------------------------------------------------------
__global__ void combine_kernel(const float* __restrict__ NC, const float* __restrict__ GB,
                               const float* __restrict__ sw, const float* __restrict__ sb,
                               float* __restrict__ out) {
    size_t idx = (size_t)blockIdx.x * blockDim.x + threadIdx.x;
    if (idx >= SZ_BCN) return;
    size_t n = idx & (Nn - 1);
    size_t bc = idx >> 12;           // / Nn
    int c = (int)(bc & (Cn - 1));
    int b = (int)(bc >> 9);          // / Cn
    size_t gidx = (((size_t)b * TWO_C + c) * Nn) + n;
    float gamma = GB[gidx];
    float beta  = GB[gidx + (size_t)Cn * Nn];
    out[idx] = (NC[idx] * sw[c] + sb[c]) * gamma + beta;
}

// ---------------------------------------------------------------------------
// Launch
// ---------------------------------------------------------------------------
extern "C" void kernel_launch(void* const* d_in, const int* in_sizes, int n_in,
                              void* d_out, int out_size) {
    const float* content = (const float*)d_in[0];
    const float* style   = (const float*)d_in[1];
    const float* Wq = (const float*)d_in[2];  const float* bq = (const float*)d_in[3];
    const float* Wk = (const float*)d_in[4];  const float* bk = (const float*)d_in[5];
    const float* Wv = (const float*)d_in[6];  const float* bv = (const float*)d_in[7];
    const float* Wg = (const float*)d_in[8];  const float* bg = (const float*)d_in[9];
    const float* Wb = (const float*)d_in[10]; const float* bb = (const float*)d_in[11];
    const float* sw = (const float*)d_in[12]; const float* sb = (const float*)d_in[13];
    float* out = (float*)d_out;

    float *NC, *NS, *Q, *K, *V, *STY, *GB, *S, *WtQ, *WtK, *WtV, *WtGB, *bGB;
    cudaGetSymbolAddress((void**)&NC, g_NC);
    cudaGetSymbolAddress((void**)&NS, g_NS);
    cudaGetSymbolAddress((void**)&Q, g_Q);
    cudaGetSymbolAddress((void**)&K, g_K);
    cudaGetSymbolAddress((void**)&V, g_V);
    cudaGetSymbolAddress((void**)&STY, g_STY);
    cudaGetSymbolAddress((void**)&GB, g_GB);
    cudaGetSymbolAddress((void**)&S, g_S);
    cudaGetSymbolAddress((void**)&WtQ, g_WtQ);
    cudaGetSymbolAddress((void**)&WtK, g_WtK);
    cudaGetSymbolAddress((void**)&WtV, g_WtV);
    cudaGetSymbolAddress((void**)&WtGB, g_WtGB);
    cudaGetSymbolAddress((void**)&bGB, g_bGB);

    const size_t sBCN = SZ_BCN;

    // 1. Weight transposes (K-major) + stacked gamma/beta weights & biases
    dim3 tb(32, 8);
    dim3 tg(Cn / 32, Cn / 32);
    transpose_kernel<<<tg, tb>>>(Wq, WtQ, Cn, Cn, Cn, 0);
    transpose_kernel<<<tg, tb>>>(Wk, WtK, Cn, Cn, Cn, 0);
    transpose_kernel<<<tg, tb>>>(Wv, WtV, Cn, Cn, Cn, 0);
    transpose_kernel<<<tg, tb>>>(Wg, WtGB, Cn, Cn, TWO_C, 0);
    transpose_kernel<<<tg, tb>>>(Wb, WtGB, Cn, Cn, TWO_C, Cn);
    biasstack_kernel<<<1, TWO_C>>>(bg, bb, bGB);

    // 2. Instance norms
    instnorm_kernel<<<Bn * Cn, 256>>>(content, NC);
    instnorm_kernel<<<Bn * Cn, 256>>>(style, NS);

    // 3. Q/K/V conv1x1 GEMMs: [C,C] x [C,N] per batch
    dim3 gconv(Nn / 128, Cn / 128, Bn);
    gemm_tn_kernel<<<gconv, 256>>>(WtQ, 0, Cn, NC, sBCN / Bn * Bn == sBCN ? (size_t)Cn * Nn : 0, Nn,
                                   Q, (size_t)Cn * Nn, Nn, bq, Cn, 0);
    gemm_tn_kernel<<<gconv, 256>>>(WtK, 0, Cn, NS, (size_t)Cn * Nn, Nn,
                                   K, (size_t)Cn * Nn, Nn, bk, Cn, 0);
    gemm_tn_kernel<<<gconv, 256>>>(WtV, 0, Cn, style, (size_t)Cn * Nn, Nn,
                                   V, (size_t)Cn * Nn, Nn, bv, Cn, 0);

    // 4. Scores: S[q,s] = sum_c Q[c,q] K[c,s]
    dim3 gsc(Nn / 128, Nn / 128, Bn);
    gemm_tn_kernel<<<gsc, 256>>>(Q, (size_t)Cn * Nn, Nn, K, (size_t)Cn * Nn, Nn,
                                 S, (size_t)Nn * Nn, Nn, nullptr, Cn, 0);

    // 5. Softmax over s
    softmax_kernel<<<Bn * Nn, 256>>>(S);

    // 6. Attention output: STY[c,q] = sum_s V[c,s] P[q,s]
    dim3 gout(Nn / 128, Cn / 128, Bn);
    gemm_nt_kernel<<<gout, 256>>>(V, (size_t)Cn * Nn, Nn, S, (size_t)Nn * Nn, Nn,
                                  STY, (size_t)Cn * Nn, Nn, Nn);

    // 7. gamma/beta stacked conv + relu: [2C,C] x [C,N] per batch
    dim3 ggb(Nn / 128, TWO_C / 128, Bn);
    gemm_tn_kernel<<<ggb, 256>>>(WtGB, 0, TWO_C, STY, (size_t)Cn * Nn, Nn,
                                 GB, (size_t)TWO_C * Nn, Nn, bGB, Cn, 1);

    // 8. Final combine
    combine_kernel<<<(unsigned)((SZ_BCN + 255) / 256), 256>>>(NC, GB, sw, sb, out);
}

// round 3
// speedup vs baseline: 2.9464x; 2.9464x over previous
#include <cuda_runtime.h>
#include <math.h>
#include <stdint.h>

#define Bn 4
#define Cn 512
#define Nn 4096
#define TWO_C 1024

constexpr size_t SZ_BCN = (size_t)Bn * Cn * Nn;
constexpr size_t SZ_GB  = (size_t)Bn * TWO_C * Nn;
constexpr size_t SZ_S   = (size_t)Bn * Nn * Nn;

// ---- scratch (static; no runtime allocation allowed) ----
__device__ float g_NC[SZ_BCN];    // inst-normed content [b][c][n]
__device__ float g_NS[SZ_BCN];    // inst-normed style   [b][c][n]
__device__ float g_NCt[SZ_BCN];   // [b][n][c]   (tf32-rounded)
__device__ float g_NSt[SZ_BCN];   // [b][n][c]   (tf32-rounded)
__device__ float g_St[SZ_BCN];    // style^T [b][s][c] (tf32-rounded)
__device__ float g_Qt[SZ_BCN];    // [b][q][c]   (tf32-rounded)
__device__ float g_Kt[SZ_BCN];    // [b][s][c]   (tf32-rounded)
__device__ float g_V[SZ_BCN];     // [b][c][s]   (tf32-rounded)
__device__ float g_STYt[SZ_BCN];  // [b][q][c]   (tf32-rounded)
__device__ float g_GB[SZ_GB];     // [b][2C][n]
__device__ float g_S[SZ_S];       // scores / probs [b][q][s]
__device__ float g_WQ[Cn * Cn];   // tf32-rounded weights
__device__ float g_WK[Cn * Cn];
__device__ float g_WV[Cn * Cn];
__device__ float g_WGB[TWO_C * Cn];
__device__ float g_bGB[TWO_C];

// ===========================================================================
// helpers
// ===========================================================================
__device__ __forceinline__ float tf32r(float x) {
    uint32_t u;
    asm("cvt.rna.tf32.f32 %0, %1;" : "=r"(u) : "f"(x));
    return __uint_as_float(u);
}
__device__ __forceinline__ uint32_t smem_u32(const void* p) {
    uint32_t a;
    asm("{ .reg .u64 t; cvta.to.shared.u64 t, %1; cvt.u32.u64 %0, t; }" : "=r"(a) : "l"(p));
    return a;
}
__device__ __forceinline__ void cpa16(uint32_t d, const float* s) {
    asm volatile("cp.async.cg.shared.global [%0], [%1], 16;\n" :: "r"(d), "l"(s));
}
#define CP_COMMIT() asm volatile("cp.async.commit_group;\n" ::: "memory")
#define CP_WAIT(n)  asm volatile("cp.async.wait_group %0;\n" :: "n"(n) : "memory")

__device__ __forceinline__ void mma_tf32(float* c, const uint32_t* a, const uint32_t* b) {
    asm volatile(
        "mma.sync.aligned.m16n8k8.row.col.f32.tf32.tf32.f32 "
        "{%0,%1,%2,%3}, {%4,%5,%6,%7}, {%8,%9}, {%0,%1,%2,%3};"
        : "+f"(c[0]), "+f"(c[1]), "+f"(c[2]), "+f"(c[3])
        : "r"(a[0]), "r"(a[1]), "r"(a[2]), "r"(a[3]), "r"(b[0]), "r"(b[1]));
}

// ===========================================================================
// tf32 mma.sync GEMM:  D[M,N] = A[M,K] * B[N,K]^T     (both K-major)
// BM=BN=128, BK=32, 3-stage cp.async, 256 threads, warp grid 2(M)x4(N),
// warp tile 64x32, m16n8k8 fragments.
// bias_mode: 0 none, 1 bias[m], 2 bias[n]. relu / round_out flags.
// ===========================================================================
#define STAGES 3
#define AROW 36                       // 32 + 4 pad floats (144B, 16B-multiple)
#define OPER_FLOATS (128 * AROW)      // 4608 floats per operand per stage
#define STG_FLOATS (2 * OPER_FLOATS)  // 9216
#define DYN_SMEM (STAGES * STG_FLOATS * 4)  // 110592 B

__global__ void __launch_bounds__(256, 2)
gemm_tc(const float* __restrict__ A, size_t sA, int lda,
        const float* __restrict__ B, size_t sB, int ldb,
        float* __restrict__ D, size_t sD, int ldd,
        const float* __restrict__ bias, int bias_mode, int relu, int round_out,
        int Kdim)
{
    extern __shared__ float smem[];
    const uint32_t sb32 = smem_u32(smem);

    const int tid = threadIdx.x;
    const int wid = tid >> 5, lane = tid & 31;
    const int gid = lane >> 2, tig = lane & 3;
    const int wm = (wid >> 2) << 6;   // 0 / 64
    const int wn = (wid & 3) << 5;    // 0 / 32 / 64 / 96
    const int m0 = blockIdx.y * 128, n0 = blockIdx.x * 128;

    const float* Ab = A + (size_t)blockIdx.z * sA;
    const float* Bb = B + (size_t)blockIdx.z * sB;

    // global->smem mapping: thread handles rows lrow+32j, 16B chunk lk
    const int lrow = tid >> 3;        // 0..31
    const int lk   = (tid & 7) << 2;  // 0..28 floats

    const float* gA = Ab + (size_t)(m0 + lrow) * lda + lk;
    const float* gB = Bb + (size_t)(n0 + lrow) * ldb + lk;
    const uint32_t dstA = sb32 + (uint32_t)(lrow * AROW + lk) * 4u;
    const uint32_t dstB = dstA + OPER_FLOATS * 4u;

    float acc[4][4][4];
#pragma unroll
    for (int i = 0; i < 4; ++i)
#pragma unroll
        for (int j = 0; j < 4; ++j)
#pragma unroll
            for (int r = 0; r < 4; ++r) acc[i][j][r] = 0.f;

    const int nk = Kdim >> 5;

    auto load_stage = [&](int kt, int sl) {
        uint32_t soff = (uint32_t)(sl * STG_FLOATS) * 4u;
        const float* ga = gA + kt * 32;
        const float* gb = gB + kt * 32;
#pragma unroll
        for (int j = 0; j < 4; ++j) {
            cpa16(dstA + soff + (uint32_t)(j * 32 * AROW) * 4u, ga + (size_t)(32 * j) * lda);
            cpa16(dstB + soff + (uint32_t)(j * 32 * AROW) * 4u, gb + (size_t)(32 * j) * ldb);
        }
    };

    load_stage(0, 0); CP_COMMIT();
    if (nk > 1) { load_stage(1, 1); CP_COMMIT(); }

    for (int ks = 0; ks < nk; ++ks) {
        if (ks == nk - 1) { CP_WAIT(0); } else { CP_WAIT(1); }
        __syncthreads();
        if (ks + 2 < nk) { load_stage(ks + 2, (ks + 2) % STAGES); CP_COMMIT(); }

        const float* As = smem + (ks % STAGES) * STG_FLOATS;
        const float* Bs = As + OPER_FLOATS;
#pragma unroll
        for (int kk = 0; kk < 4; ++kk) {
            const int k0 = kk * 8;
            uint32_t af[4][4], bf[4][2];
#pragma unroll
            for (int mt = 0; mt < 4; ++mt) {
                const float* ar = As + (wm + mt * 16 + gid) * AROW + k0 + tig;
                af[mt][0] = __float_as_uint(ar[0]);
                af[mt][1] = __float_as_uint(ar[8 * AROW]);
                af[mt][2] = __float_as_uint(ar[4]);
                af[mt][3] = __float_as_uint(ar[8 * AROW + 4]);
            }
#pragma unroll
            for (int nt = 0; nt < 4; ++nt) {
                const float* br = Bs + (wn + nt * 8 + gid) * AROW + k0 + tig;
                bf[nt][0] = __float_as_uint(br[0]);
                bf[nt][1] = __float_as_uint(br[4]);
            }
#pragma unroll
            for (int mt = 0; mt < 4; ++mt)
#pragma unroll
                for (int nt = 0; nt < 4; ++nt)
                    mma_tf32(acc[mt][nt], af[mt], bf[nt]);
        }
        __syncthreads();
    }

    // epilogue
    float* Db = D + (size_t)blockIdx.z * sD;
#pragma unroll
    for (int mt = 0; mt < 4; ++mt) {
        const int r0 = m0 + wm + mt * 16 + gid;
        const float bm0 = (bias_mode == 1) ? __ldg(&bias[r0]) : 0.f;
        const float bm1 = (bias_mode == 1) ? __ldg(&bias[r0 + 8]) : 0.f;
#pragma unroll
        for (int nt = 0; nt < 4; ++nt) {
            const int col = n0 + wn + nt * 8 + tig * 2;
            float2 bn2 = make_float2(0.f, 0.f);
            if (bias_mode == 2) bn2 = *(const float2*)(bias + col);
            float v0 = acc[mt][nt][0] + (bias_mode == 1 ? bm0 : bn2.x);
            float v1 = acc[mt][nt][1] + (bias_mode == 1 ? bm0 : bn2.y);
            float v2 = acc[mt][nt][2] + (bias_mode == 1 ? bm1 : bn2.x);
            float v3 = acc[mt][nt][3] + (bias_mode == 1 ? bm1 : bn2.y);
            if (relu) {
                v0 = fmaxf(v0, 0.f); v1 = fmaxf(v1, 0.f);
                v2 = fmaxf(v2, 0.f); v3 = fmaxf(v3, 0.f);
            }
            if (round_out) {
                v0 = tf32r(v0); v1 = tf32r(v1); v2 = tf32r(v2); v3 = tf32r(v3);
            }
            *(float2*)(Db + (size_t)r0 * ldd + col) = make_float2(v0, v1);
            *(float2*)(Db + (size_t)(r0 + 8) * ldd + col) = make_float2(v2, v3);
        }
    }
}

// ===========================================================================
// elementwise kernels
// ===========================================================================
__global__ void instnorm_kernel(const float* __restrict__ x, float* __restrict__ y) {
    const int tid = threadIdx.x;
    const size_t base = (size_t)blockIdx.x * Nn;
    float v[16];
    float s = 0.f, s2 = 0.f;
#pragma unroll
    for (int i = 0; i < 16; ++i) {
        float t = x[base + tid + i * 256];
        v[i] = t; s += t; s2 += t * t;
    }
#pragma unroll
    for (int o = 16; o > 0; o >>= 1) {
        s  += __shfl_xor_sync(0xffffffffu, s, o);
        s2 += __shfl_xor_sync(0xffffffffu, s2, o);
    }
    __shared__ float sh[16];
    int warp = tid >> 5, lane = tid & 31;
    if (lane == 0) { sh[warp] = s; sh[8 + warp] = s2; }
    __syncthreads();
    if (tid == 0) {
        float S = 0.f, S2 = 0.f;
        for (int w = 0; w < 8; ++w) { S += sh[w]; S2 += sh[8 + w]; }
        sh[0] = S; sh[8] = S2;
    }
    __syncthreads();
    float mean = sh[0] * (1.f / Nn);
    float var  = sh[8] * (1.f / Nn) - mean * mean;
    float inv  = rsqrtf(var + 1e-5f);
#pragma unroll
    for (int i = 0; i < 16; ++i)
        y[base + tid + i * 256] = (v[i] - mean) * inv;
}

// batched transpose: in [R, C2] -> out [C2, R] per batch z; optional tf32 round
__global__ void transpose_b(const float* __restrict__ in, float* __restrict__ out,
                            int R, int C2, int rnd) {
    __shared__ float t[32][33];
    const float* ib = in + (size_t)blockIdx.z * R * C2;
    float* ob = out + (size_t)blockIdx.z * R * C2;
    int c0 = blockIdx.x * 32, r0 = blockIdx.y * 32;
#pragma unroll
    for (int j = 0; j < 4; ++j)
        t[threadIdx.y + 8 * j][threadIdx.x] =
            ib[(size_t)(r0 + threadIdx.y + 8 * j) * C2 + c0 + threadIdx.x];
    __syncthreads();
#pragma unroll
    for (int j = 0; j < 4; ++j) {
        float v = t[threadIdx.x][threadIdx.y + 8 * j];
        if (rnd) v = tf32r(v);
        ob[(size_t)(c0 + threadIdx.y + 8 * j) * R + r0 + threadIdx.x] = v;
    }
}

__global__ void roundcopy_kernel(const float* __restrict__ in, float* __restrict__ out, int n) {
    int i = blockIdx.x * 256 + threadIdx.x;
    if (i < n) out[i] = tf32r(in[i]);
}

__global__ void biasstack_kernel(const float* __restrict__ bg, const float* __restrict__ bb,
                                 float* __restrict__ out) {
    int i = threadIdx.x;
    out[i] = (i < Cn) ? bg[i] : bb[i - Cn];
}

__global__ void softmax_kernel(float* __restrict__ S) {
    const int tid = threadIdx.x;
    float* row = S + (size_t)blockIdx.x * Nn;
    float v[16];
    float mx = -INFINITY;
#pragma unroll
    for (int i = 0; i < 16; ++i) {
        v[i] = row[tid + i * 256];
        mx = fmaxf(mx, v[i]);
    }
#pragma unroll
    for (int o = 16; o > 0; o >>= 1)
        mx = fmaxf(mx, __shfl_xor_sync(0xffffffffu, mx, o));
    __shared__ float sh[16];
    int warp = tid >> 5, lane = tid & 31;
    if (lane == 0) sh[warp] = mx;
    __syncthreads();
    if (tid == 0) {
        float m = sh[0];
        for (int w = 1; w < 8; ++w) m = fmaxf(m, sh[w]);
        sh[0] = m;
    }
    __syncthreads();
    mx = sh[0];
    float s = 0.f;
#pragma unroll
    for (int i = 0; i < 16; ++i) {
        v[i] = expf(v[i] - mx);
        s += v[i];
    }
#pragma unroll
    for (int o = 16; o > 0; o >>= 1)
        s += __shfl_xor_sync(0xffffffffu, s, o);
    if (lane == 0) sh[8 + warp] = s;
    __syncthreads();
    if (tid == 0) {
        float t = 0.f;
        for (int w = 0; w < 8; ++w) t += sh[8 + w];
        sh[8] = t;
    }
    __syncthreads();
    float inv = 1.f / sh[8];
#pragma unroll
    for (int i = 0; i < 16; ++i)
        row[tid + i * 256] = tf32r(v[i] * inv);   // rounded: feeds PV GEMM
}

__global__ void combine_kernel(const float* __restrict__ NC, const float* __restrict__ GB,
                               const float* __restrict__ sw, const float* __restrict__ sb,
                               float* __restrict__ out) {
    size_t idx = (size_t)blockIdx.x * blockDim.x + threadIdx.x;
    if (idx >= SZ_BCN) return;
    size_t n = idx & (Nn - 1);
    size_t bc = idx >> 12;
    int c = (int)(bc & (Cn - 1));
    int b = (int)(bc >> 9);
    size_t gidx = (((size_t)b * TWO_C + c) * Nn) + n;
    float gamma = GB[gidx];
    float beta  = GB[gidx + (size_t)Cn * Nn];
    out[idx] = (NC[idx] * sw[c] + sb[c]) * gamma + beta;
}

// ===========================================================================
// launch
// ===========================================================================
extern "C" void kernel_launch(void* const* d_in, const int* in_sizes, int n_in,
                              void* d_out, int out_size) {
    const float* content = (const float*)d_in[0];
    const float* style   = (const float*)d_in[1];
    const float* Wq = (const float*)d_in[2];  const float* bq = (const float*)d_in[3];
    const float* Wk = (const float*)d_in[4];  const float* bk = (const float*)d_in[5];
    const float* Wv = (const float*)d_in[6];  const float* bv = (const float*)d_in[7];
    const float* Wg = (const float*)d_in[8];  const float* bg = (const float*)d_in[9];
    const float* Wb = (const float*)d_in[10]; const float* bb = (const float*)d_in[11];
    const float* sw = (const float*)d_in[12]; const float* sb = (const float*)d_in[13];
    float* out = (float*)d_out;

    float *NC, *NS, *NCt, *NSt, *St, *Qt, *Kt, *V, *STYt, *GB, *S;
    float *WQ, *WK, *WV, *WGB, *bGB;
    cudaGetSymbolAddress((void**)&NC, g_NC);
    cudaGetSymbolAddress((void**)&NS, g_NS);
    cudaGetSymbolAddress((void**)&NCt, g_NCt);
    cudaGetSymbolAddress((void**)&NSt, g_NSt);
    cudaGetSymbolAddress((void**)&St, g_St);
    cudaGetSymbolAddress((void**)&Qt, g_Qt);
    cudaGetSymbolAddress((void**)&Kt, g_Kt);
    cudaGetSymbolAddress((void**)&V, g_V);
    cudaGetSymbolAddress((void**)&STYt, g_STYt);
    cudaGetSymbolAddress((void**)&GB, g_GB);
    cudaGetSymbolAddress((void**)&S, g_S);
    cudaGetSymbolAddress((void**)&WQ, g_WQ);
    cudaGetSymbolAddress((void**)&WK, g_WK);
    cudaGetSymbolAddress((void**)&WV, g_WV);
    cudaGetSymbolAddress((void**)&WGB, g_WGB);
    cudaGetSymbolAddress((void**)&bGB, g_bGB);

    static bool attr_set = false;
    if (!attr_set) {
        cudaFuncSetAttribute(gemm_tc, cudaFuncAttributeMaxDynamicSharedMemorySize, DYN_SMEM);
        attr_set = true;
    }

    const size_t strBCN = (size_t)Cn * Nn;
    const size_t strS   = (size_t)Nn * Nn;
    const size_t strGB  = (size_t)TWO_C * Nn;
    const int WN = Cn * Cn;

    // 0. rounded weight copies + stacked gamma/beta
    roundcopy_kernel<<<(WN + 255) / 256, 256>>>(Wq, WQ, WN);
    roundcopy_kernel<<<(WN + 255) / 256, 256>>>(Wk, WK, WN);
    roundcopy_kernel<<<(WN + 255) / 256, 256>>>(Wv, WV, WN);
    roundcopy_kernel<<<(WN + 255) / 256, 256>>>(Wg, WGB, WN);
    roundcopy_kernel<<<(WN + 255) / 256, 256>>>(Wb, WGB + WN, WN);
    biasstack_kernel<<<1, TWO_C>>>(bg, bb, bGB);

    // 1. instance norms
    instnorm_kernel<<<Bn * Cn, 256>>>(content, NC);
    instnorm_kernel<<<Bn * Cn, 256>>>(style, NS);

    // 2. transposes [C,N] -> [N,C] (rounded for GEMM consumption)
    dim3 tb(32, 8);
    dim3 tg(Nn / 32, Cn / 32, Bn);
    transpose_b<<<tg, tb>>>(NC, NCt, Cn, Nn, 1);
    transpose_b<<<tg, tb>>>(NS, NSt, Cn, Nn, 1);
    transpose_b<<<tg, tb>>>(style, St, Cn, Nn, 1);

    // 3. Q/K convs: Qt[q,cout] = NCt[q,c] . W[cout,c]^T (+b over cols), rounded
    dim3 gqk(Cn / 128, Nn / 128, Bn);
    gemm_tc<<<gqk, 256, DYN_SMEM>>>(NCt, strBCN, Cn, WQ, 0, Cn,
                                    Qt, strBCN, Cn, bq, 2, 0, 1, Cn);
    gemm_tc<<<gqk, 256, DYN_SMEM>>>(NSt, strBCN, Cn, WK, 0, Cn,
                                    Kt, strBCN, Cn, bk, 2, 0, 1, Cn);

    // 4. V conv: V[cout,s] = WV[cout,c] . St[s,c]^T (+bv rows), rounded
    dim3 gv(Nn / 128, Cn / 128, Bn);
    gemm_tc<<<gv, 256, DYN_SMEM>>>(WV, 0, Cn, St, strBCN, Cn,
                                   V, strBCN, Nn, bv, 1, 0, 1, Cn);

    // 5. scores: S[q,s] = Qt[q,c] . Kt[s,c]^T
    dim3 gsc(Nn / 128, Nn / 128, Bn);
    gemm_tc<<<gsc, 256, DYN_SMEM>>>(Qt, strBCN, Cn, Kt, strBCN, Cn,
                                    S, strS, Nn, nullptr, 0, 0, 0, Cn);

    // 6. softmax over s (tf32-rounded output)
    softmax_kernel<<<Bn * Nn, 256>>>(S);

    // 7. output: STYt[q,c] = P[q,s] . V[c,s]^T, rounded
    dim3 go(Cn / 128, Nn / 128, Bn);
    gemm_tc<<<go, 256, DYN_SMEM>>>(S, strS, Nn, V, strBCN, Nn,
                                   STYt, strBCN, Cn, nullptr, 0, 0, 1, Nn);

    // 8. gamma/beta: GB[c2,n] = WGB[c2,c] . STYt[n,c]^T (+bGB rows, relu)
    dim3 ggb(Nn / 128, TWO_C / 128, Bn);
    gemm_tc<<<ggb, 256, DYN_SMEM>>>(WGB, 0, Cn, STYt, strBCN, Cn,
                                    GB, strGB, Nn, bGB, 1, 1, 0, Cn);

    // 9. combine
    combine_kernel<<<(unsigned)((SZ_BCN + 255) / 256), 256>>>(NC, GB, sw, sb, out);
}

// round 4
// speedup vs baseline: 3.4549x; 1.1726x over previous
#include <cuda_runtime.h>
#include <cuda_fp16.h>
#include <math.h>
#include <stdint.h>

#define Bn 4
#define Cn 512
#define Nn 4096
#define TWO_C 1024

constexpr size_t SZ_BCN = (size_t)Bn * Cn * Nn;
constexpr size_t SZ_GB  = (size_t)Bn * TWO_C * Nn;
constexpr size_t SZ_S   = (size_t)Bn * Nn * Nn;

// ---- scratch (static; no runtime allocation allowed) ----
__device__ float  g_NC[SZ_BCN];     // inst-normed content [b][c][n] fp32
__device__ float  g_NS[SZ_BCN];     // inst-normed style   [b][c][n] fp32
__device__ __half g_NCt[SZ_BCN];    // [b][n][c]
__device__ __half g_NSt[SZ_BCN];    // [b][n][c]
__device__ __half g_St[SZ_BCN];     // style^T [b][s][c]
__device__ __half g_Qt[SZ_BCN];     // [b][q][c]
__device__ __half g_Kt[SZ_BCN];     // [b][s][c]
__device__ __half g_V[SZ_BCN];      // [b][c][s]
__device__ __half g_STYt[SZ_BCN];   // [b][q][c]
__device__ float  g_GB[SZ_GB];      // [b][2C][n] fp32
__device__ float  g_S[SZ_S];        // scores fp32; probs re-written as half in place
__device__ __half g_WQ[Cn * Cn];
__device__ __half g_WK[Cn * Cn];
__device__ __half g_WV[Cn * Cn];
__device__ __half g_WGB[TWO_C * Cn];
__device__ float  g_bGB[TWO_C];

// ===========================================================================
// helpers
// ===========================================================================
__device__ __forceinline__ uint32_t smem_u32(const void* p) {
    uint32_t a;
    asm("{ .reg .u64 t; cvta.to.shared.u64 t, %1; cvt.u32.u64 %0, t; }" : "=r"(a) : "l"(p));
    return a;
}
__device__ __forceinline__ void cpa16(uint32_t d, const void* s) {
    asm volatile("cp.async.cg.shared.global [%0], [%1], 16;\n" :: "r"(d), "l"(s));
}
#define CP_COMMIT() asm volatile("cp.async.commit_group;\n" ::: "memory")
#define CP_WAIT(n)  asm volatile("cp.async.wait_group %0;\n" :: "n"(n) : "memory")

__device__ __forceinline__ void mma_f16(float* c, const uint32_t* a, const uint32_t* b) {
    asm volatile(
        "mma.sync.aligned.m16n8k16.row.col.f32.f16.f16.f32 "
        "{%0,%1,%2,%3}, {%4,%5,%6,%7}, {%8,%9}, {%0,%1,%2,%3};"
        : "+f"(c[0]), "+f"(c[1]), "+f"(c[2]), "+f"(c[3])
        : "r"(a[0]), "r"(a[1]), "r"(a[2]), "r"(a[3]), "r"(b[0]), "r"(b[1]));
}

// ===========================================================================
// fp16 mma.sync GEMM:  D[M,N] = A[M,K] * B[N,K]^T   (both K-major, half)
// BM=BN=128, BK=64, 3-stage cp.async, 256 threads, warp grid 2(M)x4(N),
// warp tile 64x32, m16n8k16 fragments, fp32 accumulate.
// bias_mode: 0 none, 1 bias[m], 2 bias[n].  relu flag.  out_half flag.
// ===========================================================================
#define STAGES 3
#define AROW 72                        // 64 + 8 pad halfs (144 B)
#define OPER_H (128 * AROW)            // 9216 halfs per operand per stage
#define STG_H  (2 * OPER_H)            // 18432 halfs
#define DYN_SMEM (STAGES * STG_H * 2)  // 110592 B

__global__ void __launch_bounds__(256, 1)
gemm_h(const __half* __restrict__ A, size_t sA, int lda,
       const __half* __restrict__ B, size_t sB, int ldb,
       void* __restrict__ Dv, size_t sD, int ldd,
       const float* __restrict__ bias, int bias_mode, int relu, int out_half,
       int Kdim)
{
    extern __shared__ __half smem[];
    const uint32_t sb32 = smem_u32(smem);

    const int tid = threadIdx.x;
    const int wid = tid >> 5, lane = tid & 31;
    const int gid = lane >> 2, tig = lane & 3;
    const int wm = (wid >> 2) << 6;   // 0 / 64
    const int wn = (wid & 3) << 5;    // 0 / 32 / 64 / 96
    const int m0 = blockIdx.y * 128, n0 = blockIdx.x * 128;

    const __half* Ab = A + (size_t)blockIdx.z * sA;
    const __half* Bb = B + (size_t)blockIdx.z * sB;

    // global->smem mapping: 2 threads per row, each 64 consecutive bytes
    const int lrow = tid >> 1;          // 0..127
    const int lh   = (tid & 1) << 5;    // 0 or 32 halfs

    const __half* gA = Ab + (size_t)(m0 + lrow) * lda + lh;
    const __half* gB = Bb + (size_t)(n0 + lrow) * ldb + lh;
    const uint32_t dstA = sb32 + (uint32_t)(lrow * AROW + lh) * 2u;
    const uint32_t dstB = dstA + OPER_H * 2u;

    float acc[4][4][4];
#pragma unroll
    for (int i = 0; i < 4; ++i)
#pragma unroll
        for (int j = 0; j < 4; ++j)
#pragma unroll
            for (int r = 0; r < 4; ++r) acc[i][j][r] = 0.f;

    const int nk = Kdim >> 6;

    auto load_stage = [&](int kt, int sl) {
        uint32_t soff = (uint32_t)(sl * STG_H) * 2u;
        const __half* ga = gA + kt * 64;
        const __half* gb = gB + kt * 64;
#pragma unroll
        for (int j = 0; j < 4; ++j) {
            cpa16(dstA + soff + (uint32_t)(j * 16), ga + j * 8);
            cpa16(dstB + soff + (uint32_t)(j * 16), gb + j * 8);
        }
    };

    load_stage(0, 0); CP_COMMIT();
    if (nk > 1) { load_stage(1, 1); CP_COMMIT(); }

    for (int ks = 0; ks < nk; ++ks) {
        if (ks == nk - 1) { CP_WAIT(0); } else { CP_WAIT(1); }
        __syncthreads();
        if (ks + 2 < nk) { load_stage(ks + 2, (ks + 2) % STAGES); CP_COMMIT(); }

        const __half* As = smem + (ks % STAGES) * STG_H;
        const __half* Bs = As + OPER_H;
#pragma unroll
        for (int kk = 0; kk < 4; ++kk) {
            const int k0 = kk * 16;
            uint32_t af[4][4], bf[4][2];
#pragma unroll
            for (int mt = 0; mt < 4; ++mt) {
                const __half* ar = As + (wm + mt * 16 + gid) * AROW + k0 + 2 * tig;
                af[mt][0] = *(const uint32_t*)(ar);
                af[mt][1] = *(const uint32_t*)(ar + 8 * AROW);
                af[mt][2] = *(const uint32_t*)(ar + 8);
                af[mt][3] = *(const uint32_t*)(ar + 8 * AROW + 8);
            }
#pragma unroll
            for (int nt = 0; nt < 4; ++nt) {
                const __half* br = Bs + (wn + nt * 8 + gid) * AROW + k0 + 2 * tig;
                bf[nt][0] = *(const uint32_t*)(br);
                bf[nt][1] = *(const uint32_t*)(br + 8);
            }
#pragma unroll
            for (int mt = 0; mt < 4; ++mt)
#pragma unroll
                for (int nt = 0; nt < 4; ++nt)
                    mma_f16(acc[mt][nt], af[mt], bf[nt]);
        }
        __syncthreads();
    }

    // epilogue
    float*  Df = (float*)Dv  + (size_t)blockIdx.z * sD;
    __half* Dh = (__half*)Dv + (size_t)blockIdx.z * sD;
#pragma unroll
    for (int mt = 0; mt < 4; ++mt) {
        const int r0 = m0 + wm + mt * 16 + gid;
        const float bm0 = (bias_mode == 1) ? __ldg(&bias[r0]) : 0.f;
        const float bm1 = (bias_mode == 1) ? __ldg(&bias[r0 + 8]) : 0.f;
#pragma unroll
        for (int nt = 0; nt < 4; ++nt) {
            const int col = n0 + wn + nt * 8 + tig * 2;
            float2 bn2 = make_float2(0.f, 0.f);
            if (bias_mode == 2) bn2 = *(const float2*)(bias + col);
            float v0 = acc[mt][nt][0] + (bias_mode == 1 ? bm0 : bn2.x);
            float v1 = acc[mt][nt][1] + (bias_mode == 1 ? bm0 : bn2.y);
            float v2 = acc[mt][nt][2] + (bias_mode == 1 ? bm1 : bn2.x);
            float v3 = acc[mt][nt][3] + (bias_mode == 1 ? bm1 : bn2.y);
            if (relu) {
                v0 = fmaxf(v0, 0.f); v1 = fmaxf(v1, 0.f);
                v2 = fmaxf(v2, 0.f); v3 = fmaxf(v3, 0.f);
            }
            if (out_half) {
                *(__half2*)(Dh + (size_t)r0 * ldd + col) = __floats2half2_rn(v0, v1);
                *(__half2*)(Dh + (size_t)(r0 + 8) * ldd + col) = __floats2half2_rn(v2, v3);
            } else {
                *(float2*)(Df + (size_t)r0 * ldd + col) = make_float2(v0, v1);
                *(float2*)(Df + (size_t)(r0 + 8) * ldd + col) = make_float2(v2, v3);
            }
        }
    }
}

// ===========================================================================
// elementwise kernels
// ===========================================================================
__global__ void instnorm_kernel(const float* __restrict__ x, float* __restrict__ y) {
    const int tid = threadIdx.x;
    const size_t base = (size_t)blockIdx.x * Nn;
    float v[16];
    float s = 0.f, s2 = 0.f;
#pragma unroll
    for (int i = 0; i < 16; ++i) {
        float t = x[base + tid + i * 256];
        v[i] = t; s += t; s2 += t * t;
    }
#pragma unroll
    for (int o = 16; o > 0; o >>= 1) {
        s  += __shfl_xor_sync(0xffffffffu, s, o);
        s2 += __shfl_xor_sync(0xffffffffu, s2, o);
    }
    __shared__ float sh[16];
    int warp = tid >> 5, lane = tid & 31;
    if (lane == 0) { sh[warp] = s; sh[8 + warp] = s2; }
    __syncthreads();
    if (tid == 0) {
        float S = 0.f, S2 = 0.f;
        for (int w = 0; w < 8; ++w) { S += sh[w]; S2 += sh[8 + w]; }
        sh[0] = S; sh[8] = S2;
    }
    __syncthreads();
    float mean = sh[0] * (1.f / Nn);
    float var  = sh[8] * (1.f / Nn) - mean * mean;
    float inv  = rsqrtf(var + 1e-5f);
#pragma unroll
    for (int i = 0; i < 16; ++i)
        y[base + tid + i * 256] = (v[i] - mean) * inv;
}

// batched transpose with fp32 -> half: in [R, C2] -> out [C2, R] per batch z
__global__ void transpose_h(const float* __restrict__ in, __half* __restrict__ out,
                            int R, int C2) {
    __shared__ float t[32][33];
    const float* ib = in + (size_t)blockIdx.z * R * C2;
    __half* ob = out + (size_t)blockIdx.z * R * C2;
    int c0 = blockIdx.x * 32, r0 = blockIdx.y * 32;
#pragma unroll
    for (int j = 0; j < 4; ++j)
        t[threadIdx.y + 8 * j][threadIdx.x] =
            ib[(size_t)(r0 + threadIdx.y + 8 * j) * C2 + c0 + threadIdx.x];
    __syncthreads();
#pragma unroll
    for (int j = 0; j < 4; ++j)
        ob[(size_t)(c0 + threadIdx.y + 8 * j) * R + r0 + threadIdx.x] =
            __float2half_rn(t[threadIdx.x][threadIdx.y + 8 * j]);
}

__global__ void f2h_kernel(const float* __restrict__ in, __half* __restrict__ out, int n) {
    int i = blockIdx.x * 256 + threadIdx.x;
    if (i < n) out[i] = __float2half_rn(in[i]);
}

__global__ void biasstack_kernel(const float* __restrict__ bg, const float* __restrict__ bb,
                                 float* __restrict__ out) {
    int i = threadIdx.x;
    out[i] = (i < Cn) ? bg[i] : bb[i - Cn];
}

// softmax over 4096 fp32 scores; writes probs as half IN PLACE at the row start.
// All row reads happen before the first __syncthreads; writes after the last.
__global__ void softmax_kernel(float* __restrict__ S) {
    const int tid = threadIdx.x;
    float* rowf = S + (size_t)blockIdx.x * Nn;
    __half* rowh = (__half*)rowf;
    float v[16];
    float mx = -INFINITY;
#pragma unroll
    for (int i = 0; i < 16; ++i) {
        v[i] = rowf[tid + i * 256];
        mx = fmaxf(mx, v[i]);
    }
#pragma unroll
    for (int o = 16; o > 0; o >>= 1)
        mx = fmaxf(mx, __shfl_xor_sync(0xffffffffu, mx, o));
    __shared__ float sh[16];
    int warp = tid >> 5, lane = tid & 31;
    if (lane == 0) sh[warp] = mx;
    __syncthreads();
    if (tid == 0) {
        float m = sh[0];
        for (int w = 1; w < 8; ++w) m = fmaxf(m, sh[w]);
        sh[0] = m;
    }
    __syncthreads();
    mx = sh[0];
    float s = 0.f;
#pragma unroll
    for (int i = 0; i < 16; ++i) {
        v[i] = expf(v[i] - mx);
        s += v[i];
    }
#pragma unroll
    for (int o = 16; o > 0; o >>= 1)
        s += __shfl_xor_sync(0xffffffffu, s, o);
    if (lane == 0) sh[8 + warp] = s;
    __syncthreads();
    if (tid == 0) {
        float t = 0.f;
        for (int w = 0; w < 8; ++w) t += sh[8 + w];
        sh[8] = t;
    }
    __syncthreads();
    float inv = 1.f / sh[8];
#pragma unroll
    for (int i = 0; i < 16; ++i)
        rowh[tid + i * 256] = __float2half_rn(v[i] * inv);
}

__global__ void combine_kernel(const float* __restrict__ NC, const float* __restrict__ GB,
                               const float* __restrict__ sw, const float* __restrict__ sb,
                               float* __restrict__ out) {
    size_t idx = (size_t)blockIdx.x * blockDim.x + threadIdx.x;
    if (idx >= SZ_BCN) return;
    size_t n = idx & (Nn - 1);
    size_t bc = idx >> 12;
    int c = (int)(bc & (Cn - 1));
    int b = (int)(bc >> 9);
    size_t gidx = (((size_t)b * TWO_C + c) * Nn) + n;
    float gamma = GB[gidx];
    float beta  = GB[gidx + (size_t)Cn * Nn];
    out[idx] = (NC[idx] * sw[c] + sb[c]) * gamma + beta;
}

// ===========================================================================
// launch
// ===========================================================================
extern "C" void kernel_launch(void* const* d_in, const int* in_sizes, int n_in,
                              void* d_out, int out_size) {
    const float* content = (const float*)d_in[0];
    const float* style   = (const float*)d_in[1];
    const float* Wq = (const float*)d_in[2];  const float* bq = (const float*)d_in[3];
    const float* Wk = (const float*)d_in[4];  const float* bk = (const float*)d_in[5];
    const float* Wv = (const float*)d_in[6];  const float* bv = (const float*)d_in[7];
    const float* Wg = (const float*)d_in[8];  const float* bg = (const float*)d_in[9];
    const float* Wb = (const float*)d_in[10]; const float* bb = (const float*)d_in[11];
    const float* sw = (const float*)d_in[12]; const float* sb = (const float*)d_in[13];
    float* out = (float*)d_out;

    float *NC, *NS, *GB, *S, *bGB;
    __half *NCt, *NSt, *St, *Qt, *Kt, *V, *STYt, *WQ, *WK, *WV, *WGB;
    cudaGetSymbolAddress((void**)&NC, g_NC);
    cudaGetSymbolAddress((void**)&NS, g_NS);
    cudaGetSymbolAddress((void**)&NCt, g_NCt);
    cudaGetSymbolAddress((void**)&NSt, g_NSt);
    cudaGetSymbolAddress((void**)&St, g_St);
    cudaGetSymbolAddress((void**)&Qt, g_Qt);
    cudaGetSymbolAddress((void**)&Kt, g_Kt);
    cudaGetSymbolAddress((void**)&V, g_V);
    cudaGetSymbolAddress((void**)&STYt, g_STYt);
    cudaGetSymbolAddress((void**)&GB, g_GB);
    cudaGetSymbolAddress((void**)&S, g_S);
    cudaGetSymbolAddress((void**)&WQ, g_WQ);
    cudaGetSymbolAddress((void**)&WK, g_WK);
    cudaGetSymbolAddress((void**)&WV, g_WV);
    cudaGetSymbolAddress((void**)&WGB, g_WGB);
    cudaGetSymbolAddress((void**)&bGB, g_bGB);

    static bool attr_set = false;
    if (!attr_set) {
        cudaFuncSetAttribute(gemm_h, cudaFuncAttributeMaxDynamicSharedMemorySize, DYN_SMEM);
        attr_set = true;
    }

    const size_t strBCN = (size_t)Cn * Nn;
    const size_t strS   = (size_t)Nn * Nn;
    const size_t strGB  = (size_t)TWO_C * Nn;
    const int WN = Cn * Cn;

    // 0. half weights + stacked gamma/beta bias
    f2h_kernel<<<(WN + 255) / 256, 256>>>(Wq, WQ, WN);
    f2h_kernel<<<(WN + 255) / 256, 256>>>(Wk, WK, WN);
    f2h_kernel<<<(WN + 255) / 256, 256>>>(Wv, WV, WN);
    f2h_kernel<<<(WN + 255) / 256, 256>>>(Wg, WGB, WN);
    f2h_kernel<<<(WN + 255) / 256, 256>>>(Wb, WGB + WN, WN);
    biasstack_kernel<<<1, TWO_C>>>(bg, bb, bGB);

    // 1. instance norms (fp32)
    instnorm_kernel<<<Bn * Cn, 256>>>(content, NC);
    instnorm_kernel<<<Bn * Cn, 256>>>(style, NS);

    // 2. transposes [C,N] -> [N,C], half output
    dim3 tb(32, 8);
    dim3 tg(Nn / 32, Cn / 32, Bn);
    transpose_h<<<tg, tb>>>(NC, NCt, Cn, Nn);
    transpose_h<<<tg, tb>>>(NS, NSt, Cn, Nn);
    transpose_h<<<tg, tb>>>(style, St, Cn, Nn);

    // 3. Q/K convs: Qt[q,cout] = NCt[q,c] . W[cout,c]^T (+b cols), half out
    dim3 gqk(Cn / 128, Nn / 128, Bn);
    gemm_h<<<gqk, 256, DYN_SMEM>>>(NCt, strBCN, Cn, WQ, 0, Cn,
                                   Qt, strBCN, Cn, bq, 2, 0, 1, Cn);
    gemm_h<<<gqk, 256, DYN_SMEM>>>(NSt, strBCN, Cn, WK, 0, Cn,
                                   Kt, strBCN, Cn, bk, 2, 0, 1, Cn);

    // 4. V conv: V[cout,s] = WV[cout,c] . St[s,c]^T (+bv rows), half out
    dim3 gv(Nn / 128, Cn / 128, Bn);
    gemm_h<<<gv, 256, DYN_SMEM>>>(WV, 0, Cn, St, strBCN, Cn,
                                  V, strBCN, Nn, bv, 1, 0, 1, Cn);

    // 5. scores: S[q,s] = Qt[q,c] . Kt[s,c]^T  (fp32 out)
    dim3 gsc(Nn / 128, Nn / 128, Bn);
    gemm_h<<<gsc, 256, DYN_SMEM>>>(Qt, strBCN, Cn, Kt, strBCN, Cn,
                                   S, strS, Nn, nullptr, 0, 0, 0, Cn);

    // 6. softmax over s -> half probs in place (row stride 2*Nn halfs)
    softmax_kernel<<<Bn * Nn, 256>>>(S);

    // 7. output: STYt[q,c] = P[q,s] . V[c,s]^T, half out
    dim3 go(Cn / 128, Nn / 128, Bn);
    gemm_h<<<go, 256, DYN_SMEM>>>((const __half*)S, 2 * strS, 2 * Nn, V, strBCN, Nn,
                                  STYt, strBCN, Cn, nullptr, 0, 0, 1, Nn);

    // 8. gamma/beta: GB[c2,n] = WGB[c2,c] . STYt[n,c]^T (+bGB rows, relu), fp32 out
    dim3 ggb(Nn / 128, TWO_C / 128, Bn);
    gemm_h<<<ggb, 256, DYN_SMEM>>>(WGB, 0, Cn, STYt, strBCN, Cn,
                                   GB, strGB, Nn, bGB, 1, 1, 0, Cn);

    // 9. combine
    combine_kernel<<<(unsigned)((SZ_BCN + 255) / 256), 256>>>(NC, GB, sw, sb, out);
}

// round 5
// speedup vs baseline: 4.1360x; 1.1971x over previous
#include <cuda_runtime.h>
#include <cuda_fp16.h>
#include <math.h>
#include <stdint.h>

#define Bn 4
#define Cn 512
#define Nn 4096
#define TWO_C 1024
#define WN (Cn * Cn)

constexpr size_t SZ_BCN = (size_t)Bn * Cn * Nn;
constexpr size_t SZ_GB  = (size_t)Bn * TWO_C * Nn;
constexpr size_t SZ_S   = (size_t)Bn * Nn * Nn;

// ---- scratch (static; no runtime allocation allowed) ----
__device__ float  g_NC[SZ_BCN];     // inst-normed content [b][c][n] fp32
__device__ float  g_NS[SZ_BCN];     // inst-normed style   [b][c][n] fp32
__device__ __half g_NCt[SZ_BCN];    // [b][n][c]
__device__ __half g_NSt[SZ_BCN];    // [b][n][c]
__device__ __half g_St[SZ_BCN];     // style^T [b][s][c]
__device__ __half g_Qt[SZ_BCN];     // [b][q][c]
__device__ __half g_Kt[SZ_BCN];     // [b][s][c]
__device__ __half g_V[SZ_BCN];      // [b][c][s]
__device__ __half g_STYt[SZ_BCN];   // [b][q][c]
__device__ float  g_GB[SZ_GB];      // [b][2C][n] fp32
__device__ float  g_S[SZ_S];        // scores fp32; probs re-written as half in place
__device__ __half g_WQ[WN];
__device__ __half g_WK[WN];
__device__ __half g_WV[WN];
__device__ __half g_WGB[TWO_C * Cn];
__device__ float  g_bGB[TWO_C];

// ===========================================================================
// helpers
// ===========================================================================
__device__ __forceinline__ uint32_t smem_u32(const void* p) {
    uint32_t a;
    asm("{ .reg .u64 t; cvta.to.shared.u64 t, %1; cvt.u32.u64 %0, t; }" : "=r"(a) : "l"(p));
    return a;
}
__device__ __forceinline__ void cpa16(uint32_t d, const void* s) {
    asm volatile("cp.async.cg.shared.global [%0], [%1], 16;\n" :: "r"(d), "l"(s));
}
#define CP_COMMIT() asm volatile("cp.async.commit_group;\n" ::: "memory")
#define CP_WAIT(n)  asm volatile("cp.async.wait_group %0;\n" :: "n"(n) : "memory")

__device__ __forceinline__ void mma_f16(float* c, const uint32_t* a, const uint32_t* b) {
    asm volatile(
        "mma.sync.aligned.m16n8k16.row.col.f32.f16.f16.f32 "
        "{%0,%1,%2,%3}, {%4,%5,%6,%7}, {%8,%9}, {%0,%1,%2,%3};"
        : "+f"(c[0]), "+f"(c[1]), "+f"(c[2]), "+f"(c[3])
        : "r"(a[0]), "r"(a[1]), "r"(a[2]), "r"(a[3]), "r"(b[0]), "r"(b[1]));
}
__device__ __forceinline__ void ldsm_x4(uint32_t& r0, uint32_t& r1, uint32_t& r2, uint32_t& r3,
                                        uint32_t addr) {
    asm volatile("ldmatrix.sync.aligned.m8n8.x4.shared.b16 {%0,%1,%2,%3}, [%4];"
                 : "=r"(r0), "=r"(r1), "=r"(r2), "=r"(r3) : "r"(addr));
}

// ===========================================================================
// fp16 mma.sync GEMM:  D[M,N] = A[M,K] * B[N,K]^T   (both K-major, half)
// BM=BN=128, BK=64, 3-stage cp.async, 256 threads, warp grid 2(M)x4(N),
// warp tile 64x32, m16n8k16 fragments, fp32 accumulate, ldmatrix loads.
// bias_mode: 0 none, 1 bias[m], 2 bias[n].  relu flag.  out_half flag.
// ===========================================================================
#define STAGES 3
#define AROW 72                        // 64 + 8 pad halfs (144 B)
#define OPER_H (128 * AROW)            // 9216 halfs per operand per stage
#define STG_H  (2 * OPER_H)            // 18432 halfs
#define DYN_SMEM (STAGES * STG_H * 2)  // 110592 B  (x2 CTAs = 221184 <= 228KB)

__global__ void __launch_bounds__(256, 2)
gemm_h(const __half* __restrict__ A, size_t sA, int lda,
       const __half* __restrict__ B, size_t sB, int ldb,
       void* __restrict__ Dv, size_t sD, int ldd,
       const float* __restrict__ bias, int bias_mode, int relu, int out_half,
       int Kdim)
{
    extern __shared__ __half smem[];
    const uint32_t sb32 = smem_u32(smem);

    const int tid = threadIdx.x;
    const int wid = tid >> 5, lane = tid & 31;
    const int gid = lane >> 2, tig = lane & 3;
    const int wm = (wid >> 2) << 6;   // 0 / 64
    const int wn = (wid & 3) << 5;    // 0 / 32 / 64 / 96
    const int m0 = blockIdx.y * 128, n0 = blockIdx.x * 128;

    const __half* Ab = A + (size_t)blockIdx.z * sA;
    const __half* Bb = B + (size_t)blockIdx.z * sB;

    // global->smem: 2 threads per row, each 64 B
    const int lrow = tid >> 1;          // 0..127
    const int lh   = (tid & 1) << 5;    // 0 or 32 halfs

    const __half* gA = Ab + (size_t)(m0 + lrow) * lda + lh;
    const __half* gB = Bb + (size_t)(n0 + lrow) * ldb + lh;
    const uint32_t dstA = sb32 + (uint32_t)(lrow * AROW + lh) * 2u;
    const uint32_t dstB = dstA + OPER_H * 2u;

    // ldmatrix per-lane address patterns (bytes)
    const int lm = lane & 7, lq3 = (lane >> 3) & 1, lq4 = (lane >> 4) & 1;
    const uint32_t offA = (uint32_t)(((wm + lm + lq3 * 8) * AROW) + lq4 * 8) * 2u;
    const uint32_t offB = (uint32_t)(((wn + lm + lq4 * 8) * AROW) + lq3 * 8) * 2u;

    float acc[4][4][4];
#pragma unroll
    for (int i = 0; i < 4; ++i)
#pragma unroll
        for (int j = 0; j < 4; ++j)
#pragma unroll
            for (int r = 0; r < 4; ++r) acc[i][j][r] = 0.f;

    const int nk = Kdim >> 6;

    auto load_stage = [&](int kt, int sl) {
        uint32_t soff = (uint32_t)(sl * STG_H) * 2u;
        const __half* ga = gA + kt * 64;
        const __half* gb = gB + kt * 64;
#pragma unroll
        for (int j = 0; j < 4; ++j) {
            cpa16(dstA + soff + (uint32_t)(j * 16), ga + j * 8);
            cpa16(dstB + soff + (uint32_t)(j * 16), gb + j * 8);
        }
    };

    load_stage(0, 0); CP_COMMIT();
    if (nk > 1) { load_stage(1, 1); CP_COMMIT(); }

    for (int ks = 0; ks < nk; ++ks) {
        if (ks == nk - 1) { CP_WAIT(0); } else { CP_WAIT(1); }
        __syncthreads();
        if (ks + 2 < nk) { load_stage(ks + 2, (ks + 2) % STAGES); CP_COMMIT(); }

        const uint32_t As_b = sb32 + (uint32_t)((ks % STAGES) * STG_H) * 2u;
        const uint32_t Bs_b = As_b + OPER_H * 2u;
#pragma unroll
        for (int kk = 0; kk < 4; ++kk) {
            const uint32_t k0b = (uint32_t)(kk * 16) * 2u;
            uint32_t af[4][4], bf[4][2];
#pragma unroll
            for (int mt = 0; mt < 4; ++mt)
                ldsm_x4(af[mt][0], af[mt][1], af[mt][2], af[mt][3],
                        As_b + offA + (uint32_t)(mt * 16 * AROW) * 2u + k0b);
#pragma unroll
            for (int np = 0; np < 2; ++np)
                ldsm_x4(bf[2 * np][0], bf[2 * np][1], bf[2 * np + 1][0], bf[2 * np + 1][1],
                        Bs_b + offB + (uint32_t)(np * 16 * AROW) * 2u + k0b);
#pragma unroll
            for (int mt = 0; mt < 4; ++mt)
#pragma unroll
                for (int nt = 0; nt < 4; ++nt)
                    mma_f16(acc[mt][nt], af[mt], bf[nt]);
        }
        __syncthreads();
    }

    // epilogue
    float*  Df = (float*)Dv  + (size_t)blockIdx.z * sD;
    __half* Dh = (__half*)Dv + (size_t)blockIdx.z * sD;
#pragma unroll
    for (int mt = 0; mt < 4; ++mt) {
        const int r0 = m0 + wm + mt * 16 + gid;
        const float bm0 = (bias_mode == 1) ? __ldg(&bias[r0]) : 0.f;
        const float bm1 = (bias_mode == 1) ? __ldg(&bias[r0 + 8]) : 0.f;
#pragma unroll
        for (int nt = 0; nt < 4; ++nt) {
            const int col = n0 + wn + nt * 8 + tig * 2;
            float2 bn2 = make_float2(0.f, 0.f);
            if (bias_mode == 2) bn2 = *(const float2*)(bias + col);
            float v0 = acc[mt][nt][0] + (bias_mode == 1 ? bm0 : bn2.x);
            float v1 = acc[mt][nt][1] + (bias_mode == 1 ? bm0 : bn2.y);
            float v2 = acc[mt][nt][2] + (bias_mode == 1 ? bm1 : bn2.x);
            float v3 = acc[mt][nt][3] + (bias_mode == 1 ? bm1 : bn2.y);
            if (relu) {
                v0 = fmaxf(v0, 0.f); v1 = fmaxf(v1, 0.f);
                v2 = fmaxf(v2, 0.f); v3 = fmaxf(v3, 0.f);
            }
            if (out_half) {
                *(__half2*)(Dh + (size_t)r0 * ldd + col) = __floats2half2_rn(v0, v1);
                *(__half2*)(Dh + (size_t)(r0 + 8) * ldd + col) = __floats2half2_rn(v2, v3);
            } else {
                *(float2*)(Df + (size_t)r0 * ldd + col) = make_float2(v0, v1);
                *(float2*)(Df + (size_t)(r0 + 8) * ldd + col) = make_float2(v2, v3);
            }
        }
    }
}

// ===========================================================================
// elementwise kernels
// ===========================================================================
__global__ void instnorm_kernel(const float* __restrict__ x, float* __restrict__ y) {
    const int tid = threadIdx.x;
    const size_t base = (size_t)blockIdx.x * Nn;
    float v[16];
    float s = 0.f, s2 = 0.f;
#pragma unroll
    for (int i = 0; i < 16; ++i) {
        float t = x[base + tid + i * 256];
        v[i] = t; s += t; s2 += t * t;
    }
#pragma unroll
    for (int o = 16; o > 0; o >>= 1) {
        s  += __shfl_xor_sync(0xffffffffu, s, o);
        s2 += __shfl_xor_sync(0xffffffffu, s2, o);
    }
    __shared__ float sh[16];
    int warp = tid >> 5, lane = tid & 31;
    if (lane == 0) { sh[warp] = s; sh[8 + warp] = s2; }
    __syncthreads();
    if (tid == 0) {
        float S = 0.f, S2 = 0.f;
        for (int w = 0; w < 8; ++w) { S += sh[w]; S2 += sh[8 + w]; }
        sh[0] = S; sh[8] = S2;
    }
    __syncthreads();
    float mean = sh[0] * (1.f / Nn);
    float var  = sh[8] * (1.f / Nn) - mean * mean;
    float inv  = rsqrtf(var + 1e-5f);
#pragma unroll
    for (int i = 0; i < 16; ++i)
        y[base + tid + i * 256] = (v[i] - mean) * inv;
}

__global__ void transpose_h(const float* __restrict__ in, __half* __restrict__ out,
                            int R, int C2) {
    __shared__ float t[32][33];
    const float* ib = in + (size_t)blockIdx.z * R * C2;
    __half* ob = out + (size_t)blockIdx.z * R * C2;
    int c0 = blockIdx.x * 32, r0 = blockIdx.y * 32;
#pragma unroll
    for (int j = 0; j < 4; ++j)
        t[threadIdx.y + 8 * j][threadIdx.x] =
            ib[(size_t)(r0 + threadIdx.y + 8 * j) * C2 + c0 + threadIdx.x];
    __syncthreads();
#pragma unroll
    for (int j = 0; j < 4; ++j)
        ob[(size_t)(c0 + threadIdx.y + 8 * j) * R + r0 + threadIdx.x] =
            __float2half_rn(t[threadIdx.x][threadIdx.y + 8 * j]);
}

// one launch: all 5 weight conversions + bias stack
__global__ void prep_weights(const float* __restrict__ Wq, const float* __restrict__ Wk,
                             const float* __restrict__ Wv, const float* __restrict__ Wg,
                             const float* __restrict__ Wb, const float* __restrict__ bg,
                             const float* __restrict__ bb,
                             __half* __restrict__ WQ, __half* __restrict__ WK,
                             __half* __restrict__ WV, __half* __restrict__ WGB,
                             float* __restrict__ bGB) {
    int i = blockIdx.x * 256 + threadIdx.x;
    if (i < WN) {
        WQ[i] = __float2half_rn(Wq[i]);
        WK[i] = __float2half_rn(Wk[i]);
        WV[i] = __float2half_rn(Wv[i]);
        WGB[i] = __float2half_rn(Wg[i]);
        WGB[WN + i] = __float2half_rn(Wb[i]);
    }
    if (i < TWO_C) bGB[i] = (i < Cn) ? bg[i] : bb[i - Cn];
}

// softmax over 4096 fp32 scores; writes probs as half IN PLACE at the row start.
__global__ void softmax_kernel(float* __restrict__ S) {
    const int tid = threadIdx.x;
    float* rowf = S + (size_t)blockIdx.x * Nn;
    __half* rowh = (__half*)rowf;
    float v[16];
    float mx = -INFINITY;
#pragma unroll
    for (int i = 0; i < 16; ++i) {
        v[i] = rowf[tid + i * 256];
        mx = fmaxf(mx, v[i]);
    }
#pragma unroll
    for (int o = 16; o > 0; o >>= 1)
        mx = fmaxf(mx, __shfl_xor_sync(0xffffffffu, mx, o));
    __shared__ float sh[16];
    int warp = tid >> 5, lane = tid & 31;
    if (lane == 0) sh[warp] = mx;
    __syncthreads();
    if (tid == 0) {
        float m = sh[0];
        for (int w = 1; w < 8; ++w) m = fmaxf(m, sh[w]);
        sh[0] = m;
    }
    __syncthreads();
    mx = sh[0];
    float s = 0.f;
#pragma unroll
    for (int i = 0; i < 16; ++i) {
        v[i] = expf(v[i] - mx);
        s += v[i];
    }
#pragma unroll
    for (int o = 16; o > 0; o >>= 1)
        s += __shfl_xor_sync(0xffffffffu, s, o);
    if (lane == 0) sh[8 + warp] = s;
    __syncthreads();
    if (tid == 0) {
        float t = 0.f;
        for (int w = 0; w < 8; ++w) t += sh[8 + w];
        sh[8] = t;
    }
    __syncthreads();
    float inv = 1.f / sh[8];
#pragma unroll
    for (int i = 0; i < 16; ++i)
        rowh[tid + i * 256] = __float2half_rn(v[i] * inv);
}

__global__ void combine_kernel(const float* __restrict__ NC, const float* __restrict__ GB,
                               const float* __restrict__ sw, const float* __restrict__ sb,
                               float* __restrict__ out) {
    size_t idx = (size_t)blockIdx.x * blockDim.x + threadIdx.x;
    if (idx >= SZ_BCN) return;
    size_t n = idx & (Nn - 1);
    size_t bc = idx >> 12;
    int c = (int)(bc & (Cn - 1));
    int b = (int)(bc >> 9);
    size_t gidx = (((size_t)b * TWO_C + c) * Nn) + n;
    float gamma = GB[gidx];
    float beta  = GB[gidx + (size_t)Cn * Nn];
    out[idx] = (NC[idx] * sw[c] + sb[c]) * gamma + beta;
}

// ===========================================================================
// launch
// ===========================================================================
extern "C" void kernel_launch(void* const* d_in, const int* in_sizes, int n_in,
                              void* d_out, int out_size) {
    const float* content = (const float*)d_in[0];
    const float* style   = (const float*)d_in[1];
    const float* Wq = (const float*)d_in[2];  const float* bq = (const float*)d_in[3];
    const float* Wk = (const float*)d_in[4];  const float* bk = (const float*)d_in[5];
    const float* Wv = (const float*)d_in[6];  const float* bv = (const float*)d_in[7];
    const float* Wg = (const float*)d_in[8];  const float* bg = (const float*)d_in[9];
    const float* Wb = (const float*)d_in[10]; const float* bb = (const float*)d_in[11];
    const float* sw = (const float*)d_in[12]; const float* sb = (const float*)d_in[13];
    float* out = (float*)d_out;

    float *NC, *NS, *GB, *S, *bGB;
    __half *NCt, *NSt, *St, *Qt, *Kt, *V, *STYt, *WQ, *WK, *WV, *WGB;
    cudaGetSymbolAddress((void**)&NC, g_NC);
    cudaGetSymbolAddress((void**)&NS, g_NS);
    cudaGetSymbolAddress((void**)&NCt, g_NCt);
    cudaGetSymbolAddress((void**)&NSt, g_NSt);
    cudaGetSymbolAddress((void**)&St, g_St);
    cudaGetSymbolAddress((void**)&Qt, g_Qt);
    cudaGetSymbolAddress((void**)&Kt, g_Kt);
    cudaGetSymbolAddress((void**)&V, g_V);
    cudaGetSymbolAddress((void**)&STYt, g_STYt);
    cudaGetSymbolAddress((void**)&GB, g_GB);
    cudaGetSymbolAddress((void**)&S, g_S);
    cudaGetSymbolAddress((void**)&WQ, g_WQ);
    cudaGetSymbolAddress((void**)&WK, g_WK);
    cudaGetSymbolAddress((void**)&WV, g_WV);
    cudaGetSymbolAddress((void**)&WGB, g_WGB);
    cudaGetSymbolAddress((void**)&bGB, g_bGB);

    static bool attr_set = false;
    if (!attr_set) {
        cudaFuncSetAttribute(gemm_h, cudaFuncAttributeMaxDynamicSharedMemorySize, DYN_SMEM);
        attr_set = true;
    }

    const size_t strBCN = (size_t)Cn * Nn;
    const size_t strS   = (size_t)Nn * Nn;
    const size_t strGB  = (size_t)TWO_C * Nn;

    // 0. weights -> half, stacked bias (one launch)
    prep_weights<<<(WN + 255) / 256, 256>>>(Wq, Wk, Wv, Wg, Wb, bg, bb,
                                            WQ, WK, WV, WGB, bGB);

    // 1. instance norms (fp32)
    instnorm_kernel<<<Bn * Cn, 256>>>(content, NC);
    instnorm_kernel<<<Bn * Cn, 256>>>(style, NS);

    // 2. transposes [C,N] -> [N,C], half output
    dim3 tb(32, 8);
    dim3 tg(Nn / 32, Cn / 32, Bn);
    transpose_h<<<tg, tb>>>(NC, NCt, Cn, Nn);
    transpose_h<<<tg, tb>>>(NS, NSt, Cn, Nn);
    transpose_h<<<tg, tb>>>(style, St, Cn, Nn);

    // 3. Q/K convs: Qt[q,cout] = NCt[q,c] . W[cout,c]^T (+b cols), half out
    dim3 gqk(Cn / 128, Nn / 128, Bn);
    gemm_h<<<gqk, 256, DYN_SMEM>>>(NCt, strBCN, Cn, WQ, 0, Cn,
                                   Qt, strBCN, Cn, bq, 2, 0, 1, Cn);
    gemm_h<<<gqk, 256, DYN_SMEM>>>(NSt, strBCN, Cn, WK, 0, Cn,
                                   Kt, strBCN, Cn, bk, 2, 0, 1, Cn);

    // 4. V conv: V[cout,s] = WV[cout,c] . St[s,c]^T (+bv rows), half out
    dim3 gv(Nn / 128, Cn / 128, Bn);
    gemm_h<<<gv, 256, DYN_SMEM>>>(WV, 0, Cn, St, strBCN, Cn,
                                  V, strBCN, Nn, bv, 1, 0, 1, Cn);

    // 5. scores: S[q,s] = Qt[q,c] . Kt[s,c]^T  (fp32 out)
    dim3 gsc(Nn / 128, Nn / 128, Bn);
    gemm_h<<<gsc, 256, DYN_SMEM>>>(Qt, strBCN, Cn, Kt, strBCN, Cn,
                                   S, strS, Nn, nullptr, 0, 0, 0, Cn);

    // 6. softmax over s -> half probs in place (row stride 2*Nn halfs)
    softmax_kernel<<<Bn * Nn, 256>>>(S);

    // 7. output: STYt[q,c] = P[q,s] . V[c,s]^T, half out
    dim3 go(Cn / 128, Nn / 128, Bn);
    gemm_h<<<go, 256, DYN_SMEM>>>((const __half*)S, 2 * strS, 2 * Nn, V, strBCN, Nn,
                                  STYt, strBCN, Cn, nullptr, 0, 0, 1, Nn);

    // 8. gamma/beta: GB[c2,n] = WGB[c2,c] . STYt[n,c]^T (+bGB rows, relu), fp32 out
    dim3 ggb(Nn / 128, TWO_C / 128, Bn);
    gemm_h<<<ggb, 256, DYN_SMEM>>>(WGB, 0, Cn, STYt, strBCN, Cn,
                                   GB, strGB, Nn, bGB, 1, 1, 0, Cn);

    // 9. combine
    combine_kernel<<<(unsigned)((SZ_BCN + 255) / 256), 256>>>(NC, GB, sw, sb, out);
}

// round 6
// speedup vs baseline: 4.3702x; 1.0566x over previous
#include <cuda_runtime.h>
#include <cuda_fp16.h>
#include <math.h>
#include <stdint.h>

#define Bn 4
#define Cn 512
#define Nn 4096
#define TWO_C 1024
#define WN (Cn * Cn)

constexpr size_t SZ_BCN = (size_t)Bn * Cn * Nn;
constexpr size_t SZ_GB  = (size_t)Bn * TWO_C * Nn;
constexpr size_t SZ_S   = (size_t)Bn * Nn * Nn;

// ---- scratch (static; no runtime allocation allowed) ----
__device__ __half g_NCt[SZ_BCN];    // normed content^T [b][n][c]
__device__ __half g_NSt[SZ_BCN];    // normed style^T   [b][n][c]
__device__ __half g_St[SZ_BCN];     // raw style^T      [b][s][c]
__device__ __half g_Qt[SZ_BCN];     // [b][q][c]
__device__ __half g_Kt[SZ_BCN];     // [b][s][c]
__device__ __half g_V[SZ_BCN];      // [b][c][s]
__device__ __half g_STYt[SZ_BCN];   // [b][q][c]
__device__ float  g_GB[SZ_GB];      // [b][2C][n]
__device__ float  g_S[SZ_S];        // scores fp32; probs re-written half in place
__device__ __half g_WQ[WN];
__device__ __half g_WK[WN];
__device__ __half g_WV[WN];
__device__ __half g_WGB[TWO_C * Cn];
__device__ float  g_bGB[TWO_C];
__device__ float2 g_stats[2 * Bn * Cn];   // (mean, inv_std): [0]=content, [1]=style

// ===========================================================================
// helpers
// ===========================================================================
__device__ __forceinline__ uint32_t smem_u32(const void* p) {
    uint32_t a;
    asm("{ .reg .u64 t; cvta.to.shared.u64 t, %1; cvt.u32.u64 %0, t; }" : "=r"(a) : "l"(p));
    return a;
}
__device__ __forceinline__ void cpa16(uint32_t d, const void* s) {
    asm volatile("cp.async.cg.shared.global [%0], [%1], 16;\n" :: "r"(d), "l"(s));
}
#define CP_COMMIT() asm volatile("cp.async.commit_group;\n" ::: "memory")
#define CP_WAIT(n)  asm volatile("cp.async.wait_group %0;\n" :: "n"(n) : "memory")

__device__ __forceinline__ void mma_f16(float* c, const uint32_t* a, const uint32_t* b) {
    asm volatile(
        "mma.sync.aligned.m16n8k16.row.col.f32.f16.f16.f32 "
        "{%0,%1,%2,%3}, {%4,%5,%6,%7}, {%8,%9}, {%0,%1,%2,%3};"
        : "+f"(c[0]), "+f"(c[1]), "+f"(c[2]), "+f"(c[3])
        : "r"(a[0]), "r"(a[1]), "r"(a[2]), "r"(a[3]), "r"(b[0]), "r"(b[1]));
}
__device__ __forceinline__ void ldsm_x4(uint32_t& r0, uint32_t& r1, uint32_t& r2, uint32_t& r3,
                                        uint32_t addr) {
    asm volatile("ldmatrix.sync.aligned.m8n8.x4.shared.b16 {%0,%1,%2,%3}, [%4];"
                 : "=r"(r0), "=r"(r1), "=r"(r2), "=r"(r3) : "r"(addr));
}

// ===========================================================================
// fp16 mma.sync GEMM core:  D[M,N] = A[M,K] * B[N,K]^T (K-major half)
// BM=BN=128, BK=64, 3-stage cp.async, 256 threads, warp 64x32 tile.
// ===========================================================================
#define STAGES 3
#define AROW 72
#define OPER_H (128 * AROW)
#define STG_H  (2 * OPER_H)
#define DYN_SMEM (STAGES * STG_H * 2)

__device__ __forceinline__ void
gemm_core(const __half* __restrict__ A, int lda,
          const __half* __restrict__ B, int ldb,
          void* __restrict__ Dv, int ldd,
          const float* __restrict__ bias, int bias_mode, int relu, int out_half,
          int Kdim, int m0, int n0, __half* smem)
{
    const uint32_t sb32 = smem_u32(smem);
    const int tid = threadIdx.x;
    const int wid = tid >> 5, lane = tid & 31;
    const int gid = lane >> 2, tig = lane & 3;
    const int wm = (wid >> 2) << 6;
    const int wn = (wid & 3) << 5;

    const int lrow = tid >> 1;
    const int lh   = (tid & 1) << 5;

    const __half* gA = A + (size_t)(m0 + lrow) * lda + lh;
    const __half* gB = B + (size_t)(n0 + lrow) * ldb + lh;
    const uint32_t dstA = sb32 + (uint32_t)(lrow * AROW + lh) * 2u;
    const uint32_t dstB = dstA + OPER_H * 2u;

    const int lm = lane & 7, lq3 = (lane >> 3) & 1, lq4 = (lane >> 4) & 1;
    const uint32_t offA = (uint32_t)(((wm + lm + lq3 * 8) * AROW) + lq4 * 8) * 2u;
    const uint32_t offB = (uint32_t)(((wn + lm + lq4 * 8) * AROW) + lq3 * 8) * 2u;

    float acc[4][4][4];
#pragma unroll
    for (int i = 0; i < 4; ++i)
#pragma unroll
        for (int j = 0; j < 4; ++j)
#pragma unroll
            for (int r = 0; r < 4; ++r) acc[i][j][r] = 0.f;

    const int nk = Kdim >> 6;

    auto load_stage = [&](int kt, int sl) {
        uint32_t soff = (uint32_t)(sl * STG_H) * 2u;
        const __half* ga = gA + kt * 64;
        const __half* gb = gB + kt * 64;
#pragma unroll
        for (int j = 0; j < 4; ++j) {
            cpa16(dstA + soff + (uint32_t)(j * 16), ga + j * 8);
            cpa16(dstB + soff + (uint32_t)(j * 16), gb + j * 8);
        }
    };

    load_stage(0, 0); CP_COMMIT();
    if (nk > 1) { load_stage(1, 1); CP_COMMIT(); }

    for (int ks = 0; ks < nk; ++ks) {
        if (ks == nk - 1) { CP_WAIT(0); } else { CP_WAIT(1); }
        __syncthreads();
        if (ks + 2 < nk) { load_stage(ks + 2, (ks + 2) % STAGES); CP_COMMIT(); }

        const uint32_t As_b = sb32 + (uint32_t)((ks % STAGES) * STG_H) * 2u;
        const uint32_t Bs_b = As_b + OPER_H * 2u;
#pragma unroll
        for (int kk = 0; kk < 4; ++kk) {
            const uint32_t k0b = (uint32_t)(kk * 16) * 2u;
            uint32_t af[4][4], bf[4][2];
#pragma unroll
            for (int mt = 0; mt < 4; ++mt)
                ldsm_x4(af[mt][0], af[mt][1], af[mt][2], af[mt][3],
                        As_b + offA + (uint32_t)(mt * 16 * AROW) * 2u + k0b);
#pragma unroll
            for (int np = 0; np < 2; ++np)
                ldsm_x4(bf[2 * np][0], bf[2 * np][1], bf[2 * np + 1][0], bf[2 * np + 1][1],
                        Bs_b + offB + (uint32_t)(np * 16 * AROW) * 2u + k0b);
#pragma unroll
            for (int mt = 0; mt < 4; ++mt)
#pragma unroll
                for (int nt = 0; nt < 4; ++nt)
                    mma_f16(acc[mt][nt], af[mt], bf[nt]);
        }
        __syncthreads();
    }

    float*  Df = (float*)Dv;
    __half* Dh = (__half*)Dv;
#pragma unroll
    for (int mt = 0; mt < 4; ++mt) {
        const int r0 = m0 + wm + mt * 16 + gid;
        const float bm0 = (bias_mode == 1) ? __ldg(&bias[r0]) : 0.f;
        const float bm1 = (bias_mode == 1) ? __ldg(&bias[r0 + 8]) : 0.f;
#pragma unroll
        for (int nt = 0; nt < 4; ++nt) {
            const int col = n0 + wn + nt * 8 + tig * 2;
            float2 bn2 = make_float2(0.f, 0.f);
            if (bias_mode == 2) bn2 = *(const float2*)(bias + col);
            float v0 = acc[mt][nt][0] + (bias_mode == 1 ? bm0 : bn2.x);
            float v1 = acc[mt][nt][1] + (bias_mode == 1 ? bm0 : bn2.y);
            float v2 = acc[mt][nt][2] + (bias_mode == 1 ? bm1 : bn2.x);
            float v3 = acc[mt][nt][3] + (bias_mode == 1 ? bm1 : bn2.y);
            if (relu) {
                v0 = fmaxf(v0, 0.f); v1 = fmaxf(v1, 0.f);
                v2 = fmaxf(v2, 0.f); v3 = fmaxf(v3, 0.f);
            }
            if (out_half) {
                *(__half2*)(Dh + (size_t)r0 * ldd + col) = __floats2half2_rn(v0, v1);
                *(__half2*)(Dh + (size_t)(r0 + 8) * ldd + col) = __floats2half2_rn(v2, v3);
            } else {
                *(float2*)(Df + (size_t)r0 * ldd + col) = make_float2(v0, v1);
                *(float2*)(Df + (size_t)(r0 + 8) * ldd + col) = make_float2(v2, v3);
            }
        }
    }
}

// generic batched GEMM (scores / PV / GB)
__global__ void __launch_bounds__(256, 2)
gemm_h(const __half* __restrict__ A, size_t sA, int lda,
       const __half* __restrict__ B, size_t sB, int ldb,
       void* __restrict__ Dv, size_t sD, int ldd, int d_half,
       const float* __restrict__ bias, int bias_mode, int relu, int Kdim)
{
    extern __shared__ __half smem[];
    void* Dp = d_half ? (void*)((__half*)Dv + (size_t)blockIdx.z * sD)
                      : (void*)((float*)Dv + (size_t)blockIdx.z * sD);
    gemm_core(A + (size_t)blockIdx.z * sA, lda,
              B + (size_t)blockIdx.z * sB, ldb,
              Dp, ldd, bias, bias_mode, relu, d_half, Kdim,
              blockIdx.y * 128, blockIdx.x * 128, smem);
}

// fused Q/K/V convs: grid (32, 4, 12). z: [0,4)=Q, [4,8)=K, [8,12)=V (z&3 = batch)
__global__ void __launch_bounds__(256, 2)
qkv_gemm(const __half* __restrict__ NCt, const __half* __restrict__ NSt,
         const __half* __restrict__ St,
         const __half* __restrict__ WQ, const __half* __restrict__ WK,
         const __half* __restrict__ WV,
         __half* __restrict__ Qt, __half* __restrict__ Kt, __half* __restrict__ V,
         const float* __restrict__ bq, const float* __restrict__ bk,
         const float* __restrict__ bv)
{
    extern __shared__ __half smem[];
    const int g = blockIdx.z >> 2;      // 0=Q 1=K 2=V
    const size_t boff = (size_t)(blockIdx.z & 3) * ((size_t)Cn * Nn);

    if (g < 2) {
        const __half* A = (g == 0 ? NCt : NSt) + boff;
        const __half* B = (g == 0 ? WQ : WK);
        __half* D = (g == 0 ? Qt : Kt) + boff;
        const float* bias = (g == 0 ? bq : bk);
        gemm_core(A, Cn, B, Cn, D, Cn, bias, 2, 0, 1, Cn,
                  blockIdx.x * 128, blockIdx.y * 128, smem);
    } else {
        gemm_core(WV, Cn, St + boff, Cn, V + boff, Nn, bv, 1, 0, 1, Cn,
                  blockIdx.y * 128, blockIdx.x * 128, smem);
    }
}

// ===========================================================================
// elementwise
// ===========================================================================
// per-(b,c) mean / inv-std for content (first half) and style (second half)
__global__ void stats_kernel(const float* __restrict__ content,
                             const float* __restrict__ style,
                             float2* __restrict__ stats) {
    const int id = blockIdx.x;                  // 0 .. 2*Bn*Cn-1
    const float* x = (id < Bn * Cn) ? content : style;
    const size_t base = (size_t)(id & (Bn * Cn - 1)) * Nn;
    const int tid = threadIdx.x;
    float s = 0.f, s2 = 0.f;
#pragma unroll
    for (int i = 0; i < 16; ++i) {
        float t = x[base + tid + i * 256];
        s += t; s2 += t * t;
    }
#pragma unroll
    for (int o = 16; o > 0; o >>= 1) {
        s  += __shfl_xor_sync(0xffffffffu, s, o);
        s2 += __shfl_xor_sync(0xffffffffu, s2, o);
    }
    __shared__ float sh[16];
    int warp = tid >> 5, lane = tid & 31;
    if (lane == 0) { sh[warp] = s; sh[8 + warp] = s2; }
    __syncthreads();
    if (tid == 0) {
        float S = 0.f, S2 = 0.f;
        for (int w = 0; w < 8; ++w) { S += sh[w]; S2 += sh[8 + w]; }
        float mean = S * (1.f / Nn);
        float var  = S2 * (1.f / Nn) - mean * mean;
        stats[id] = make_float2(mean, rsqrtf(var + 1e-5f));
    }
}

// fused transpose (+ optional norm) fp32[C,N] -> half[N,C]
// grid (Nn/32, Cn/32, 3*Bn): z>>2 : 0=content->NCt(norm) 1=style->NSt(norm) 2=style->St(raw)
__global__ void transpose_nh(const float* __restrict__ content,
                             const float* __restrict__ style,
                             const float2* __restrict__ stats,
                             __half* __restrict__ NCt, __half* __restrict__ NSt,
                             __half* __restrict__ St) {
    __shared__ float t[32][33];
    const int g = blockIdx.z >> 2;
    const int b = blockIdx.z & 3;
    const float* in = (g == 0) ? content : style;
    __half* out = (g == 0) ? NCt : (g == 1) ? NSt : St;
    const float2* st = (g == 0) ? stats : (g == 1) ? stats + Bn * Cn : nullptr;

    const float* ib = in + (size_t)b * Cn * Nn;
    __half* ob = out + (size_t)b * Cn * Nn;
    int c0 = blockIdx.x * 32, r0 = blockIdx.y * 32;
#pragma unroll
    for (int j = 0; j < 4; ++j) {
        int c = r0 + threadIdx.y + 8 * j;
        float v = ib[(size_t)c * Nn + c0 + threadIdx.x];
        if (g < 2) {
            float2 ms = __ldg(&st[b * Cn + c]);
            v = (v - ms.x) * ms.y;
        }
        t[threadIdx.y + 8 * j][threadIdx.x] = v;
    }
    __syncthreads();
#pragma unroll
    for (int j = 0; j < 4; ++j)
        ob[(size_t)(c0 + threadIdx.y + 8 * j) * Cn + r0 + threadIdx.x] =
            __float2half_rn(t[threadIdx.x][threadIdx.y + 8 * j]);
}

__global__ void prep_weights(const float* __restrict__ Wq, const float* __restrict__ Wk,
                             const float* __restrict__ Wv, const float* __restrict__ Wg,
                             const float* __restrict__ Wb, const float* __restrict__ bg,
                             const float* __restrict__ bb,
                             __half* __restrict__ WQ, __half* __restrict__ WK,
                             __half* __restrict__ WV, __half* __restrict__ WGB,
                             float* __restrict__ bGB) {
    int i = blockIdx.x * 256 + threadIdx.x;
    if (i < WN) {
        WQ[i] = __float2half_rn(Wq[i]);
        WK[i] = __float2half_rn(Wk[i]);
        WV[i] = __float2half_rn(Wv[i]);
        WGB[i] = __float2half_rn(Wg[i]);
        WGB[WN + i] = __float2half_rn(Wb[i]);
    }
    if (i < TWO_C) bGB[i] = (i < Cn) ? bg[i] : bb[i - Cn];
}

// softmax over 4096 fp32 scores; writes half probs IN PLACE at the row start
__global__ void softmax_kernel(float* __restrict__ S) {
    const int tid = threadIdx.x;
    float* rowf = S + (size_t)blockIdx.x * Nn;
    __half* rowh = (__half*)rowf;
    float v[16];
    float mx = -INFINITY;
#pragma unroll
    for (int i = 0; i < 16; ++i) {
        v[i] = rowf[tid + i * 256];
        mx = fmaxf(mx, v[i]);
    }
#pragma unroll
    for (int o = 16; o > 0; o >>= 1)
        mx = fmaxf(mx, __shfl_xor_sync(0xffffffffu, mx, o));
    __shared__ float sh[16];
    int warp = tid >> 5, lane = tid & 31;
    if (lane == 0) sh[warp] = mx;
    __syncthreads();
    if (tid == 0) {
        float m = sh[0];
        for (int w = 1; w < 8; ++w) m = fmaxf(m, sh[w]);
        sh[0] = m;
    }
    __syncthreads();
    mx = sh[0];
    float s = 0.f;
#pragma unroll
    for (int i = 0; i < 16; ++i) {
        v[i] = expf(v[i] - mx);
        s += v[i];
    }
#pragma unroll
    for (int o = 16; o > 0; o >>= 1)
        s += __shfl_xor_sync(0xffffffffu, s, o);
    if (lane == 0) sh[8 + warp] = s;
    __syncthreads();
    if (tid == 0) {
        float t = 0.f;
        for (int w = 0; w < 8; ++w) t += sh[8 + w];
        sh[8] = t;
    }
    __syncthreads();
    float inv = 1.f / sh[8];
#pragma unroll
    for (int i = 0; i < 16; ++i)
        rowh[tid + i * 256] = __float2half_rn(v[i] * inv);
}

// out = ((content - mean)*inv * sw[c] + sb[c]) * gamma + beta   (float4)
__global__ void combine_kernel(const float* __restrict__ content,
                               const float2* __restrict__ stats,
                               const float* __restrict__ GB,
                               const float* __restrict__ sw, const float* __restrict__ sb,
                               float* __restrict__ out) {
    size_t i4 = (size_t)blockIdx.x * blockDim.x + threadIdx.x;   // float4 index
    size_t idx = i4 * 4;
    if (idx >= SZ_BCN) return;
    size_t n = idx & (Nn - 1);
    size_t bc = idx >> 12;
    int c = (int)(bc & (Cn - 1));
    int b = (int)(bc >> 9);
    float2 ms = __ldg(&stats[b * Cn + c]);
    float w = sw[c] * ms.y;
    float base = sb[c] - ms.x * ms.y * sw[c];
    size_t gidx = (((size_t)b * TWO_C + c) * Nn) + n;
    float4 x = *(const float4*)(content + idx);
    float4 gm = *(const float4*)(GB + gidx);
    float4 bt = *(const float4*)(GB + gidx + (size_t)Cn * Nn);
    float4 r;
    r.x = (x.x * w + base) * gm.x + bt.x;
    r.y = (x.y * w + base) * gm.y + bt.y;
    r.z = (x.z * w + base) * gm.z + bt.z;
    r.w = (x.w * w + base) * gm.w + bt.w;
    *(float4*)(out + idx) = r;
}

// ===========================================================================
// launch
// ===========================================================================
extern "C" void kernel_launch(void* const* d_in, const int* in_sizes, int n_in,
                              void* d_out, int out_size) {
    const float* content = (const float*)d_in[0];
    const float* style   = (const float*)d_in[1];
    const float* Wq = (const float*)d_in[2];  const float* bq = (const float*)d_in[3];
    const float* Wk = (const float*)d_in[4];  const float* bk = (const float*)d_in[5];
    const float* Wv = (const float*)d_in[6];  const float* bv = (const float*)d_in[7];
    const float* Wg = (const float*)d_in[8];  const float* bg = (const float*)d_in[9];
    const float* Wb = (const float*)d_in[10]; const float* bb = (const float*)d_in[11];
    const float* sw = (const float*)d_in[12]; const float* sb = (const float*)d_in[13];
    float* out = (float*)d_out;

    float *GB, *S, *bGB;
    float2* stats;
    __half *NCt, *NSt, *St, *Qt, *Kt, *V, *STYt, *WQ, *WK, *WV, *WGB;
    cudaGetSymbolAddress((void**)&NCt, g_NCt);
    cudaGetSymbolAddress((void**)&NSt, g_NSt);
    cudaGetSymbolAddress((void**)&St, g_St);
    cudaGetSymbolAddress((void**)&Qt, g_Qt);
    cudaGetSymbolAddress((void**)&Kt, g_Kt);
    cudaGetSymbolAddress((void**)&V, g_V);
    cudaGetSymbolAddress((void**)&STYt, g_STYt);
    cudaGetSymbolAddress((void**)&GB, g_GB);
    cudaGetSymbolAddress((void**)&S, g_S);
    cudaGetSymbolAddress((void**)&WQ, g_WQ);
    cudaGetSymbolAddress((void**)&WK, g_WK);
    cudaGetSymbolAddress((void**)&WV, g_WV);
    cudaGetSymbolAddress((void**)&WGB, g_WGB);
    cudaGetSymbolAddress((void**)&bGB, g_bGB);
    cudaGetSymbolAddress((void**)&stats, g_stats);

    static bool attr_set = false;
    if (!attr_set) {
        cudaFuncSetAttribute(gemm_h, cudaFuncAttributeMaxDynamicSharedMemorySize, DYN_SMEM);
        cudaFuncSetAttribute(qkv_gemm, cudaFuncAttributeMaxDynamicSharedMemorySize, DYN_SMEM);
        attr_set = true;
    }

    const size_t strBCN = (size_t)Cn * Nn;
    const size_t strS   = (size_t)Nn * Nn;
    const size_t strGB  = (size_t)TWO_C * Nn;

    // 0. weights -> half, stacked bias
    prep_weights<<<(WN + 255) / 256, 256>>>(Wq, Wk, Wv, Wg, Wb, bg, bb,
                                            WQ, WK, WV, WGB, bGB);

    // 1. per-channel stats (content + style)
    stats_kernel<<<2 * Bn * Cn, 256>>>(content, style, stats);

    // 2. fused norm+transpose (content->NCt, style->NSt, style raw->St)
    dim3 tb(32, 8);
    dim3 tg(Nn / 32, Cn / 32, 3 * Bn);
    transpose_nh<<<tg, tb>>>(content, style, stats, NCt, NSt, St);

    // 3. fused Q/K/V convs
    qkv_gemm<<<dim3(32, 4, 12), 256, DYN_SMEM>>>(NCt, NSt, St, WQ, WK, WV,
                                                 Qt, Kt, V, bq, bk, bv);

    // 4. scores: S[q,s] = Qt[q,c] . Kt[s,c]^T  (fp32 out)
    gemm_h<<<dim3(32, 32, Bn), 256, DYN_SMEM>>>(Qt, strBCN, Cn, Kt, strBCN, Cn,
                                                S, strS, Nn, 0, nullptr, 0, 0, Cn);

    // 5. softmax -> half probs in place (row stride 2*Nn halfs)
    softmax_kernel<<<Bn * Nn, 256>>>(S);

    // 6. PV: STYt[q,c] = P[q,s] . V[c,s]^T, half out
    gemm_h<<<dim3(4, 32, Bn), 256, DYN_SMEM>>>((const __half*)S, 2 * strS, 2 * Nn,
                                               V, strBCN, Nn,
                                               STYt, strBCN, Cn, 1, nullptr, 0, 0, Nn);

    // 7. gamma/beta: GB[c2,n] = WGB[c2,c] . STYt[n,c]^T (+bGB rows, relu), fp32 out
    gemm_h<<<dim3(32, 8, Bn), 256, DYN_SMEM>>>(WGB, 0, Cn, STYt, strBCN, Cn,
                                               GB, strGB, Nn, 0, bGB, 1, 1, Cn);

    // 8. combine
    combine_kernel<<<(unsigned)((SZ_BCN / 4 + 255) / 256), 256>>>(
        content, stats, GB, sw, sb, out);
}